// round 1
// baseline (speedup 1.0000x reference)
#include <cuda_runtime.h>
#include <cuda_bf16.h>
#include <math.h>

#define B_ 4
#define N_ 2048
#define NB_ 10
#define P_ 5
#define CPD 16   // 15 dims padded to 16 for float4
#define CH 128   // m-chunk staged in smem

// ---------------- scratch (no allocations allowed) ----------------
__device__ float g_pred_cp[B_*N_*CPD];
__device__ float g_gt_cp  [B_*N_*CPD];
__device__ float g_sym_cp [B_*N_*CPD];
__device__ float g_best   [B_*N_];   // pred->gt masked min of min(d1,d2)
__device__ float g_contrib[B_*N_];   // gt->pred: succ*conf*min(m1,m2)
__device__ float g_ew     [B_*N_];   // succ*(cos_d + cos_a + off)
__device__ float g_sbce   [B_*N_];   // score bce per point

__device__ __forceinline__ float softplusf(float x) {
    return fmaxf(x, 0.0f) + log1pf(expf(-fabsf(x)));
}

// ---------------- kernel 1: build control points + elementwise ----------------
__global__ void prep_kernel(
    const float* __restrict__ gd,   // grasp_dir_head      (B,N,3)
    const float* __restrict__ ad,   // approach_dir_head   (B,N,3)
    const float* __restrict__ goh,  // grasp_offset_head   (B,N,NB)
    const float* __restrict__ pp,   // pred_points         (B,N,3)
    const float* __restrict__ bsh,  // binary_score_head   (B,N,1)
    const float* __restrict__ dl,   // dir_labels_pc_cam   (B,N,3)
    const float* __restrict__ ol,   // offset_labels_pc    (B,N,NB)
    const float* __restrict__ succ, // (B,N)
    const float* __restrict__ al,   // approach_labels     (B,N,3)
    const float* __restrict__ bv,   // bin_vals (NB)
    const float* __restrict__ bw,   // bin_weights (NB)
    const float* __restrict__ cp,   // control_pts (P,3)
    const float* __restrict__ scp)  // sym_control_pts (P,3)
{
    int i = blockIdx.x * blockDim.x + threadIdx.x;
    if (i >= B_ * N_) return;

    float bx = gd[i*3+0], by = gd[i*3+1], bz = gd[i*3+2];   // base = grasp_dir
    float ax = ad[i*3+0], ay = ad[i*3+1], az = ad[i*3+2];   // approach
    float px = pp[i*3+0], py = pp[i*3+1], pz = pp[i*3+2];

    // thickness_pred: argmax over NB (first max)
    float x0 = goh[i*NB_];
    int kp = 0; float xm = x0;
    #pragma unroll
    for (int k = 1; k < NB_; k++) {
        float v = goh[i*NB_+k];
        if (v > xm) { xm = v; kp = k; }
    }
    float thp = bv[kp];

    // thickness_gt: argmax of one-hot labels
    int kg = 0; float ym = ol[i*NB_];
    #pragma unroll
    for (int k = 1; k < NB_; k++) {
        float v = ol[i*NB_+k];
        if (v > ym) { ym = v; kg = k; }
    }
    float thg = bv[kg];

    // pred grasp: cross = approach x base
    float cx = ay*bz - az*by;
    float cy = az*bx - ax*bz;
    float cz = ax*by - ay*bx;
    float tx = px + 0.5f*thp*bx;
    float ty = py + 0.5f*thp*by;
    float tz = pz + 0.5f*thp*bz;

    float* po = g_pred_cp + (size_t)i * CPD;
    #pragma unroll
    for (int p = 0; p < P_; p++) {
        float c0 = cp[p*3+0], c1 = cp[p*3+1], c2 = cp[p*3+2];
        po[p*3+0] = bx*c0 + cx*c1 + ax*c2 + tx;
        po[p*3+1] = by*c0 + cy*c1 + ay*c2 + ty;
        po[p*3+2] = bz*c0 + cz*c1 + az*c2 + tz;
    }
    po[15] = 0.0f;

    // gt grasp
    float gbx = dl[i*3+0], gby = dl[i*3+1], gbz = dl[i*3+2];
    float gax = al[i*3+0], gay = al[i*3+1], gaz = al[i*3+2];
    float gcx = gay*gbz - gaz*gby;
    float gcy = gaz*gbx - gax*gbz;
    float gcz = gax*gby - gay*gbx;
    float gtx = px + 0.5f*thg*gbx;
    float gty = py + 0.5f*thg*gby;
    float gtz = pz + 0.5f*thg*gbz;

    float* go = g_gt_cp + (size_t)i * CPD;
    float* so = g_sym_cp + (size_t)i * CPD;
    #pragma unroll
    for (int p = 0; p < P_; p++) {
        float c0 = cp[p*3+0], c1 = cp[p*3+1], c2 = cp[p*3+2];
        go[p*3+0] = gbx*c0 + gcx*c1 + gax*c2 + gtx;
        go[p*3+1] = gby*c0 + gcy*c1 + gay*c2 + gty;
        go[p*3+2] = gbz*c0 + gcz*c1 + gaz*c2 + gtz;
        float s0 = scp[p*3+0], s1 = scp[p*3+1], s2 = scp[p*3+2];
        so[p*3+0] = gbx*s0 + gcx*s1 + gax*s2 + gtx;
        so[p*3+1] = gby*s0 + gcy*s1 + gay*s2 + gty;
        so[p*3+2] = gbz*s0 + gcz*s1 + gaz*s2 + gtz;
    }
    go[15] = 0.0f;
    so[15] = 0.0f;

    // elementwise losses
    float s = succ[i];
    float cos_d = 1.0f - (gbx*bx + gby*by + gbz*bz);   // dir_labels . grasp_dir

    // orthogonalize approach_labels against grasp_dir
    float proj = bx*gax + by*gay + bz*gaz;
    float ox = gax - proj*bx;
    float oy = gay - proj*by;
    float oz = gaz - proj*bz;
    float on = sqrtf(ox*ox + oy*oy + oz*oz);
    float inv = 1.0f / fmaxf(on, 1e-12f);
    float cos_a = 1.0f - (ox*ax + oy*ay + oz*az) * inv;

    float off = 0.0f;
    #pragma unroll
    for (int k = 0; k < NB_; k++) {
        float x = goh[i*NB_+k];
        float y = ol[i*NB_+k];
        float bce = y * softplusf(-x) + (1.0f - y) * softplusf(x);
        off += bw[k] * bce;
    }
    off *= (1.0f / NB_);

    g_ew[i] = s * (cos_d + cos_a + off);

    float h = bsh[i];
    g_sbce[i] = s * softplusf(-h) + (1.0f - s) * softplusf(h);
}

// ---------------- kernel 2a: pred->gt masked min ----------------
// block: 256 threads = 32 n-slots x 8 m-lanes; grid (N/32, B)
__global__ void best_kernel(const float* __restrict__ succ)
{
    int b  = blockIdx.y;
    int tid = threadIdx.x;
    int ns = tid >> 3;
    int ml = tid & 7;
    int n  = blockIdx.x * 32 + ns;

    const float4* prow = (const float4*)(g_pred_cp + ((size_t)b*N_ + n) * CPD);
    float4 pr0 = prow[0], pr1 = prow[1], pr2 = prow[2], pr3 = prow[3];

    __shared__ float4 sg[CH*4];
    __shared__ float4 ss[CH*4];
    __shared__ float  sm[CH];

    float minv = INFINITY;

    for (int mc = 0; mc < N_; mc += CH) {
        __syncthreads();
        const float4* gsrc = (const float4*)(g_gt_cp  + ((size_t)b*N_ + mc) * CPD);
        const float4* ssrc = (const float4*)(g_sym_cp + ((size_t)b*N_ + mc) * CPD);
        for (int j = tid; j < CH*4; j += 256) { sg[j] = gsrc[j]; ss[j] = ssrc[j]; }
        for (int j = tid; j < CH;   j += 256) sm[j] = succ[(size_t)b*N_ + mc + j];
        __syncthreads();

        #pragma unroll 4
        for (int j = 0; j < CH/8; j++) {
            int m = ml + j*8;
            float4 g0 = sg[m*4+0], g1 = sg[m*4+1], g2 = sg[m*4+2], g3 = sg[m*4+3];
            float4 s0 = ss[m*4+0], s1 = ss[m*4+1], s2 = ss[m*4+2], s3 = ss[m*4+3];
            float d1 = 0.f, d2 = 0.f, t;
            t = pr0.x-g0.x; d1 += t*t;  t = pr0.y-g0.y; d1 += t*t;
            t = pr0.z-g0.z; d1 += t*t;  t = pr0.w-g0.w; d1 += t*t;
            t = pr1.x-g1.x; d1 += t*t;  t = pr1.y-g1.y; d1 += t*t;
            t = pr1.z-g1.z; d1 += t*t;  t = pr1.w-g1.w; d1 += t*t;
            t = pr2.x-g2.x; d1 += t*t;  t = pr2.y-g2.y; d1 += t*t;
            t = pr2.z-g2.z; d1 += t*t;  t = pr2.w-g2.w; d1 += t*t;
            t = pr3.x-g3.x; d1 += t*t;  t = pr3.y-g3.y; d1 += t*t;
            t = pr3.z-g3.z; d1 += t*t;  t = pr3.w-g3.w; d1 += t*t;

            t = pr0.x-s0.x; d2 += t*t;  t = pr0.y-s0.y; d2 += t*t;
            t = pr0.z-s0.z; d2 += t*t;  t = pr0.w-s0.w; d2 += t*t;
            t = pr1.x-s1.x; d2 += t*t;  t = pr1.y-s1.y; d2 += t*t;
            t = pr1.z-s1.z; d2 += t*t;  t = pr1.w-s1.w; d2 += t*t;
            t = pr2.x-s2.x; d2 += t*t;  t = pr2.y-s2.y; d2 += t*t;
            t = pr2.z-s2.z; d2 += t*t;  t = pr2.w-s2.w; d2 += t*t;
            t = pr3.x-s3.x; d2 += t*t;  t = pr3.y-s3.y; d2 += t*t;
            t = pr3.z-s3.z; d2 += t*t;  t = pr3.w-s3.w; d2 += t*t;

            float dm = fminf(d1, d2);
            if (sm[m] > 0.5f) minv = fminf(minv, dm);
        }
    }

    // reduce min across the 8 m-lanes (groups of 8 consecutive lanes)
    minv = fminf(minv, __shfl_down_sync(0xffffffffu, minv, 4));
    minv = fminf(minv, __shfl_down_sync(0xffffffffu, minv, 2));
    minv = fminf(minv, __shfl_down_sync(0xffffffffu, minv, 1));
    if (ml == 0) g_best[(size_t)b*N_ + n] = minv;
}

// ---------------- kernel 2b: gt->pred min + argmin (both matrices) ----------------
__global__ void g2p_kernel(const float* __restrict__ succ,
                           const float* __restrict__ bsp)
{
    int b  = blockIdx.y;
    int tid = threadIdx.x;
    int ns = tid >> 3;
    int ml = tid & 7;
    int g  = blockIdx.x * 32 + ns;

    const float4* grow = (const float4*)(g_gt_cp  + ((size_t)b*N_ + g) * CPD);
    const float4* srow = (const float4*)(g_sym_cp + ((size_t)b*N_ + g) * CPD);
    float4 gr0 = grow[0], gr1 = grow[1], gr2 = grow[2], gr3 = grow[3];
    float4 sr0 = srow[0], sr1 = srow[1], sr2 = srow[2], sr3 = srow[3];

    __shared__ float4 sp_[CH*4];

    unsigned long long best1 = 0xFFFFFFFFFFFFFFFFull;
    unsigned long long best2 = 0xFFFFFFFFFFFFFFFFull;

    for (int pc = 0; pc < N_; pc += CH) {
        __syncthreads();
        const float4* psrc = (const float4*)(g_pred_cp + ((size_t)b*N_ + pc) * CPD);
        for (int j = tid; j < CH*4; j += 256) sp_[j] = psrc[j];
        __syncthreads();

        #pragma unroll 4
        for (int j = 0; j < CH/8; j++) {
            int p = ml + j*8;
            float4 p0 = sp_[p*4+0], p1 = sp_[p*4+1], p2 = sp_[p*4+2], p3 = sp_[p*4+3];
            float d1 = 0.f, d2 = 0.f, t;
            t = gr0.x-p0.x; d1 += t*t;  t = gr0.y-p0.y; d1 += t*t;
            t = gr0.z-p0.z; d1 += t*t;  t = gr0.w-p0.w; d1 += t*t;
            t = gr1.x-p1.x; d1 += t*t;  t = gr1.y-p1.y; d1 += t*t;
            t = gr1.z-p1.z; d1 += t*t;  t = gr1.w-p1.w; d1 += t*t;
            t = gr2.x-p2.x; d1 += t*t;  t = gr2.y-p2.y; d1 += t*t;
            t = gr2.z-p2.z; d1 += t*t;  t = gr2.w-p2.w; d1 += t*t;
            t = gr3.x-p3.x; d1 += t*t;  t = gr3.y-p3.y; d1 += t*t;
            t = gr3.z-p3.z; d1 += t*t;  t = gr3.w-p3.w; d1 += t*t;

            t = sr0.x-p0.x; d2 += t*t;  t = sr0.y-p0.y; d2 += t*t;
            t = sr0.z-p0.z; d2 += t*t;  t = sr0.w-p0.w; d2 += t*t;
            t = sr1.x-p1.x; d2 += t*t;  t = sr1.y-p1.y; d2 += t*t;
            t = sr1.z-p1.z; d2 += t*t;  t = sr1.w-p1.w; d2 += t*t;
            t = sr2.x-p2.x; d2 += t*t;  t = sr2.y-p2.y; d2 += t*t;
            t = sr2.z-p2.z; d2 += t*t;  t = sr2.w-p2.w; d2 += t*t;
            t = sr3.x-p3.x; d2 += t*t;  t = sr3.y-p3.y; d2 += t*t;
            t = sr3.z-p3.z; d2 += t*t;  t = sr3.w-p3.w; d2 += t*t;

            unsigned long long k1 = ((unsigned long long)__float_as_uint(d1) << 32) | (unsigned)(pc + p);
            unsigned long long k2 = ((unsigned long long)__float_as_uint(d2) << 32) | (unsigned)(pc + p);
            if (k1 < best1) best1 = k1;
            if (k2 < best2) best2 = k2;
        }
    }

    // min over 8 lanes (packed => min value, tie -> smallest index = first occurrence)
    {
        unsigned long long o;
        o = __shfl_down_sync(0xffffffffu, best1, 4); if (o < best1) best1 = o;
        o = __shfl_down_sync(0xffffffffu, best1, 2); if (o < best1) best1 = o;
        o = __shfl_down_sync(0xffffffffu, best1, 1); if (o < best1) best1 = o;
        o = __shfl_down_sync(0xffffffffu, best2, 4); if (o < best2) best2 = o;
        o = __shfl_down_sync(0xffffffffu, best2, 2); if (o < best2) best2 = o;
        o = __shfl_down_sync(0xffffffffu, best2, 1); if (o < best2) best2 = o;
    }

    if (ml == 0) {
        float m1 = __uint_as_float((unsigned)(best1 >> 32));
        float m2 = __uint_as_float((unsigned)(best2 >> 32));
        int i1 = (int)(best1 & 0xFFFFFFFFu);
        int i2 = (int)(best2 & 0xFFFFFFFFu);
        int idx = (m2 < m1) ? i2 : i1;
        float mmin = fminf(m1, m2);
        float s = succ[(size_t)b*N_ + g];
        g_contrib[(size_t)b*N_ + g] = s * bsp[(size_t)b*N_ + idx] * mmin;
    }
}

// ---------------- kernel 3: final reduction ----------------
__device__ __forceinline__ float blockReduceSum(float v, float* red, int tid) {
    __syncthreads();
    red[tid] = v;
    __syncthreads();
    for (int s = 512; s > 0; s >>= 1) {
        if (tid < s) red[tid] += red[tid + s];
        __syncthreads();
    }
    float r = red[0];
    __syncthreads();
    return r;
}

__global__ void finalize_kernel(const float* __restrict__ succ,
                                const float* __restrict__ bsp,
                                float* __restrict__ out)
{
    __shared__ float red[1024];
    __shared__ float s_piv[B_], s_gate[B_];
    int tid = threadIdx.x;

    // pass 1: succ sums per batch
    float ps[B_] = {0.f, 0.f, 0.f, 0.f};
    for (int i = tid; i < B_*N_; i += 1024) ps[i >> 11] += succ[i];
    for (int b = 0; b < B_; b++) {
        float r = blockReduceSum(ps[b], red, tid);
        if (tid == 0) { s_piv[b] = fmaxf(r, 1.0f); s_gate[b] = fminf(r, 1.0f); }
    }
    __syncthreads();

    // pass 2: everything else
    float aew[B_]  = {0.f, 0.f, 0.f, 0.f};
    float ag2p[B_] = {0.f, 0.f, 0.f, 0.f};
    float padds = 0.f, pbce = 0.f;
    for (int i = tid; i < B_*N_; i += 1024) {
        int b = i >> 11;
        aew[b]  += g_ew[i];
        ag2p[b] += g_contrib[i];
        float ma = (s_gate[b] > 0.f) ? sqrtf(g_best[i]) : 0.f;
        padds += bsp[i] * ma;
        pbce  += g_sbce[i];
    }

    float r_aew[B_], r_g2p[B_];
    for (int b = 0; b < B_; b++) r_aew[b] = blockReduceSum(aew[b], red, tid);
    for (int b = 0; b < B_; b++) r_g2p[b] = blockReduceSum(ag2p[b], red, tid);
    float r_adds = blockReduceSum(padds, red, tid);
    float r_bce  = blockReduceSum(pbce, red, tid);

    if (tid == 0) {
        float t = 0.f;
        for (int b = 0; b < B_; b++)
            t += (r_aew[b] + r_g2p[b]) / s_piv[b];
        t *= (1.0f / B_);
        t += 10.0f * r_adds * (1.0f / (B_ * N_));
        t += r_bce * (1.0f / (B_ * N_));
        out[0] = t;
    }
}

// ---------------- launch ----------------
extern "C" void kernel_launch(void* const* d_in, const int* in_sizes, int n_in,
                              void* d_out, int out_size)
{
    const float* gd   = (const float*)d_in[0];   // grasp_dir_head
    const float* ad   = (const float*)d_in[1];   // approach_dir_head
    const float* goh  = (const float*)d_in[2];   // grasp_offset_head
    const float* pp   = (const float*)d_in[3];   // pred_points
    const float* bsp  = (const float*)d_in[4];   // binary_score_pred
    const float* bsh  = (const float*)d_in[5];   // binary_score_head
    const float* dl   = (const float*)d_in[6];   // dir_labels_pc_cam
    const float* ol   = (const float*)d_in[7];   // offset_labels_pc
    const float* succ = (const float*)d_in[8];   // grasp_success_labels_pc
    const float* al   = (const float*)d_in[9];   // approach_labels_pc_cam
    const float* bv   = (const float*)d_in[10];  // bin_vals
    const float* bw   = (const float*)d_in[11];  // bin_weights
    const float* cp   = (const float*)d_in[12];  // control_pts
    const float* scp  = (const float*)d_in[13];  // sym_control_pts
    float* out = (float*)d_out;

    prep_kernel<<<(B_*N_ + 255) / 256, 256>>>(gd, ad, goh, pp, bsh, dl, ol, succ, al, bv, bw, cp, scp);
    dim3 grid2(N_ / 32, B_);
    best_kernel<<<grid2, 256>>>(succ);
    g2p_kernel<<<grid2, 256>>>(succ, bsp);
    finalize_kernel<<<1, 1024>>>(succ, bsp, out);
}

// round 2
// speedup vs baseline: 3.0080x; 3.0080x over previous
#include <cuda_runtime.h>
#include <math.h>

#define B_ 4
#define N_ 2048
#define NB_ 10
#define P_ 5
#define CPD 16   // 15 dims + norm in slot 15
#define CH 128   // streamed points per smem tile
#define NT 4     // fixed rows per thread

// ---------------- scratch (no allocations allowed) ----------------
__device__ float g_pred_cp[B_*N_*CPD];
__device__ float g_gt_cp  [B_*N_*CPD];
__device__ float g_best   [B_*N_];   // pred->gt masked min of min(d1,d2)
__device__ float g_contrib[B_*N_];   // gt->pred: succ*conf*min(m1,m2)
__device__ float g_ew     [B_*N_];   // succ*(cos_d + cos_a + off)
__device__ float g_sbce   [B_*N_];   // score bce per point

typedef unsigned long long ull;

__device__ __forceinline__ ull pack2(float lo, float hi) {
    ull r; asm("mov.b64 %0,{%1,%2};" : "=l"(r) : "f"(lo), "f"(hi)); return r;
}
__device__ __forceinline__ void unpack2(ull v, float& lo, float& hi) {
    asm("mov.b64 {%0,%1},%2;" : "=f"(lo), "=f"(hi) : "l"(v));
}
__device__ __forceinline__ ull fma2(ull a, ull b, ull c) {
    ull d; asm("fma.rn.f32x2 %0,%1,%2,%3;" : "=l"(d) : "l"(a), "l"(b), "l"(c)); return d;
}
__device__ __forceinline__ ull mul2(ull a, ull b) {
    ull d; asm("mul.rn.f32x2 %0,%1,%2;" : "=l"(d) : "l"(a), "l"(b)); return d;
}
__device__ __forceinline__ ull add2(ull a, ull b) {
    ull d; asm("add.rn.f32x2 %0,%1,%2;" : "=l"(d) : "l"(a), "l"(b)); return d;
}

__device__ __forceinline__ float softplusf(float x) {
    return fmaxf(x, 0.0f) + log1pf(expf(-fabsf(x)));
}

#define F_INF __int_as_float(0x7f800000)

// ---------------- kernel 1: build control points (+norm in slot15) + elementwise ----------------
__global__ void prep_kernel(
    const float* __restrict__ gd,   // grasp_dir_head      (B,N,3)
    const float* __restrict__ ad,   // approach_dir_head   (B,N,3)
    const float* __restrict__ goh,  // grasp_offset_head   (B,N,NB)
    const float* __restrict__ pp,   // pred_points         (B,N,3)
    const float* __restrict__ bsh,  // binary_score_head   (B,N,1)
    const float* __restrict__ dl,   // dir_labels_pc_cam   (B,N,3)
    const float* __restrict__ ol,   // offset_labels_pc    (B,N,NB)
    const float* __restrict__ succ, // (B,N)
    const float* __restrict__ al,   // approach_labels     (B,N,3)
    const float* __restrict__ bv,   // bin_vals (NB)
    const float* __restrict__ bw,   // bin_weights (NB)
    const float* __restrict__ cp)   // control_pts (P,3)
{
    int i = blockIdx.x * blockDim.x + threadIdx.x;
    if (i >= B_ * N_) return;

    float bx = gd[i*3+0], by = gd[i*3+1], bz = gd[i*3+2];   // base = grasp_dir
    float ax = ad[i*3+0], ay = ad[i*3+1], az = ad[i*3+2];   // approach
    float px = pp[i*3+0], py = pp[i*3+1], pz = pp[i*3+2];

    // thickness_pred: argmax over NB (first max)
    int kp = 0; float xm = goh[i*NB_];
    #pragma unroll
    for (int k = 1; k < NB_; k++) {
        float v = goh[i*NB_+k];
        if (v > xm) { xm = v; kp = k; }
    }
    float thp = bv[kp];

    // thickness_gt: argmax of one-hot labels
    int kg = 0; float ym = ol[i*NB_];
    #pragma unroll
    for (int k = 1; k < NB_; k++) {
        float v = ol[i*NB_+k];
        if (v > ym) { ym = v; kg = k; }
    }
    float thg = bv[kg];

    // pred grasp: cross = approach x base
    float cx = ay*bz - az*by;
    float cy = az*bx - ax*bz;
    float cz = ax*by - ay*bx;
    float tx = px + 0.5f*thp*bx;
    float ty = py + 0.5f*thp*by;
    float tz = pz + 0.5f*thp*bz;

    {
        float row[16];
        float nrm = 0.0f;
        #pragma unroll
        for (int p = 0; p < P_; p++) {
            float c0 = cp[p*3+0], c1 = cp[p*3+1], c2 = cp[p*3+2];
            float vx = bx*c0 + cx*c1 + ax*c2 + tx;
            float vy = by*c0 + cy*c1 + ay*c2 + ty;
            float vz = bz*c0 + cz*c1 + az*c2 + tz;
            row[p*3+0] = vx; row[p*3+1] = vy; row[p*3+2] = vz;
            nrm += vx*vx + vy*vy + vz*vz;
        }
        row[15] = nrm;
        float4* po = (float4*)(g_pred_cp + (size_t)i * CPD);
        #pragma unroll
        for (int q = 0; q < 4; q++)
            po[q] = make_float4(row[q*4+0], row[q*4+1], row[q*4+2], row[q*4+3]);
    }

    // gt grasp
    float gbx = dl[i*3+0], gby = dl[i*3+1], gbz = dl[i*3+2];
    float gax = al[i*3+0], gay = al[i*3+1], gaz = al[i*3+2];
    float gcx = gay*gbz - gaz*gby;
    float gcy = gaz*gbx - gax*gbz;
    float gcz = gax*gby - gay*gbx;
    float gtx = px + 0.5f*thg*gbx;
    float gty = py + 0.5f*thg*gby;
    float gtz = pz + 0.5f*thg*gbz;

    {
        float row[16];
        float nrm = 0.0f;
        #pragma unroll
        for (int p = 0; p < P_; p++) {
            float c0 = cp[p*3+0], c1 = cp[p*3+1], c2 = cp[p*3+2];
            float vx = gbx*c0 + gcx*c1 + gax*c2 + gtx;
            float vy = gby*c0 + gcy*c1 + gay*c2 + gty;
            float vz = gbz*c0 + gcz*c1 + gaz*c2 + gtz;
            row[p*3+0] = vx; row[p*3+1] = vy; row[p*3+2] = vz;
            nrm += vx*vx + vy*vy + vz*vz;
        }
        row[15] = nrm;
        float4* go = (float4*)(g_gt_cp + (size_t)i * CPD);
        #pragma unroll
        for (int q = 0; q < 4; q++)
            go[q] = make_float4(row[q*4+0], row[q*4+1], row[q*4+2], row[q*4+3]);
    }

    // elementwise losses
    float s = succ[i];
    float cos_d = 1.0f - (gbx*bx + gby*by + gbz*bz);   // dir_labels . grasp_dir

    // orthogonalize approach_labels against grasp_dir
    float proj = bx*gax + by*gay + bz*gaz;
    float ox = gax - proj*bx;
    float oy = gay - proj*by;
    float oz = gaz - proj*bz;
    float on = sqrtf(ox*ox + oy*oy + oz*oz);
    float inv = 1.0f / fmaxf(on, 1e-12f);
    float cos_a = 1.0f - (ox*ax + oy*ay + oz*az) * inv;

    float off = 0.0f;
    #pragma unroll
    for (int k = 0; k < NB_; k++) {
        float x = goh[i*NB_+k];
        float y = ol[i*NB_+k];
        float bce = y * softplusf(-x) + (1.0f - y) * softplusf(x);
        off += bw[k] * bce;
    }
    off *= (1.0f / NB_);

    g_ew[i] = s * (cos_d + cos_a + off);

    float h = bsh[i];
    g_sbce[i] = s * softplusf(-h) + (1.0f - s) * softplusf(h);
}

// ---------------- kernel 2: both pairwise directions in one launch ----------------
// grid (N_/(32*NT), B_, 2): z=0 pred->gt masked min (dir A); z=1 gt->pred argmin (dir B)
// block 256 = 32 n-slots x 8 m-lanes; each thread handles NT fixed rows.
// Distances use  d1 = ||f||^2 + ||s||^2 - 2 f.s  (norms precomputed in slot 15),
// and the sym variant via the point-2<->3 swap identity:
//   d2 = d1 + 2 * dot(Delta_f, Delta_s),   Delta = (x6-x9, x7-x10, x8-x11).
__global__ __launch_bounds__(256, 1) void pair_kernel(const float* __restrict__ succ,
                                                      const float* __restrict__ bsp)
{
    __shared__ float4 sg[CH*5];     // stride-5 padding -> conflict-free lane reads
    __shared__ float  smask[CH];

    int b   = blockIdx.y;
    bool dB = (blockIdx.z != 0);
    int tid = threadIdx.x;
    int ns  = tid >> 3;
    int ml  = tid & 7;

    const float* fx = dB ? g_gt_cp   : g_pred_cp;  // fixed rows
    const float* st = dB ? g_pred_cp : g_gt_cp;    // streamed rows

    ull  FP[NT][7];
    float f14[NT], fn[NT], fD0[NT], fD1[NT], fD2[NT];
    int  nrow[NT];

    #pragma unroll
    for (int r = 0; r < NT; r++) {
        int n = blockIdx.x * (32*NT) + r*32 + ns;
        nrow[r] = n;
        const float4* row = (const float4*)(fx + ((size_t)b*N_ + n) * CPD);
        float4 a0 = row[0], a1 = row[1], a2 = row[2], a3 = row[3];
        FP[r][0] = pack2(a0.x, a0.y);
        FP[r][1] = pack2(a0.z, a0.w);
        FP[r][2] = pack2(a1.x, a1.y);
        FP[r][3] = pack2(a1.z, a1.w);
        FP[r][4] = pack2(a2.x, a2.y);
        FP[r][5] = pack2(a2.z, a2.w);
        FP[r][6] = pack2(a3.x, a3.y);
        f14[r] = a3.z;            // dim 14
        fn[r]  = a3.w;            // ||f||^2
        fD0[r] = a1.z - a2.y;     // x6 - x9
        fD1[r] = a1.w - a2.z;     // x7 - x10
        fD2[r] = a2.x - a2.w;     // x8 - x11
    }

    float minv[NT];
    ull   b1[NT], b2[NT];
    #pragma unroll
    for (int r = 0; r < NT; r++) {
        minv[r] = F_INF;
        b1[r] = 0xFFFFFFFFFFFFFFFFull;
        b2[r] = 0xFFFFFFFFFFFFFFFFull;
    }

    for (int mc = 0; mc < N_; mc += CH) {
        __syncthreads();
        const float4* src = (const float4*)(st + ((size_t)b*N_ + mc) * CPD);
        #pragma unroll
        for (int j = tid; j < CH*4; j += 256)
            sg[(j >> 2) * 5 + (j & 3)] = src[j];
        if (!dB && tid < CH) smask[tid] = succ[(size_t)b*N_ + mc + tid];
        __syncthreads();

        #pragma unroll 2
        for (int j = 0; j < CH/8; j++) {
            int m = ml + j*8;
            const float4* sp = &sg[m*5];
            float4 s0 = sp[0], s1 = sp[1], s2 = sp[2], s3 = sp[3];
            ull S0 = pack2(s0.x, s0.y);
            ull S1 = pack2(s0.z, s0.w);
            ull S2 = pack2(s1.x, s1.y);
            ull S3 = pack2(s1.z, s1.w);
            ull S4 = pack2(s2.x, s2.y);
            ull S5 = pack2(s2.z, s2.w);
            ull S6 = pack2(s3.x, s3.y);
            float s14 = s3.z, sn = s3.w;
            float D0 = s1.z - s2.y;
            float D1 = s1.w - s2.z;
            float D2 = s2.x - s2.w;
            float msk = dB ? 0.0f : smask[m];

            #pragma unroll
            for (int r = 0; r < NT; r++) {
                ull a = mul2(FP[r][0], S0);
                ull c = mul2(FP[r][1], S1);
                a = fma2(FP[r][2], S2, a);
                c = fma2(FP[r][3], S3, c);
                a = fma2(FP[r][4], S4, a);
                c = fma2(FP[r][5], S5, c);
                a = fma2(FP[r][6], S6, a);
                a = add2(a, c);
                float lo, hi; unpack2(a, lo, hi);
                float dot  = fmaf(f14[r], s14, lo + hi);
                float d1   = fmaf(-2.0f, dot, fn[r] + sn);
                float corr = fD0[r] * D0;
                corr = fmaf(fD1[r], D1, corr);
                corr = fmaf(fD2[r], D2, corr);
                float d2 = fmaf(2.0f, corr, d1);
                d1 = fmaxf(d1, 0.0f);
                d2 = fmaxf(d2, 0.0f);
                if (!dB) {
                    float dm = fminf(d1, d2);
                    minv[r] = fminf(minv[r], (msk > 0.5f) ? dm : F_INF);
                } else {
                    unsigned idx = (unsigned)(mc + m);
                    ull k1 = ((ull)__float_as_uint(d1) << 32) | idx;
                    ull k2 = ((ull)__float_as_uint(d2) << 32) | idx;
                    if (k1 < b1[r]) b1[r] = k1;
                    if (k2 < b2[r]) b2[r] = k2;
                }
            }
        }
    }

    if (!dB) {
        #pragma unroll
        for (int r = 0; r < NT; r++) {
            float v = minv[r];
            v = fminf(v, __shfl_down_sync(0xffffffffu, v, 4));
            v = fminf(v, __shfl_down_sync(0xffffffffu, v, 2));
            v = fminf(v, __shfl_down_sync(0xffffffffu, v, 1));
            if (ml == 0) g_best[(size_t)b*N_ + nrow[r]] = v;
        }
    } else {
        #pragma unroll
        for (int r = 0; r < NT; r++) {
            ull v1 = b1[r], v2 = b2[r], o;
            o = __shfl_down_sync(0xffffffffu, v1, 4); if (o < v1) v1 = o;
            o = __shfl_down_sync(0xffffffffu, v1, 2); if (o < v1) v1 = o;
            o = __shfl_down_sync(0xffffffffu, v1, 1); if (o < v1) v1 = o;
            o = __shfl_down_sync(0xffffffffu, v2, 4); if (o < v2) v2 = o;
            o = __shfl_down_sync(0xffffffffu, v2, 2); if (o < v2) v2 = o;
            o = __shfl_down_sync(0xffffffffu, v2, 1); if (o < v2) v2 = o;
            if (ml == 0) {
                float m1 = __uint_as_float((unsigned)(v1 >> 32));
                float m2 = __uint_as_float((unsigned)(v2 >> 32));
                int   i1 = (int)(v1 & 0xFFFFFFFFu);
                int   i2 = (int)(v2 & 0xFFFFFFFFu);
                int  idx = (m2 < m1) ? i2 : i1;
                float mm = fminf(m1, m2);
                float s  = succ[(size_t)b*N_ + nrow[r]];
                g_contrib[(size_t)b*N_ + nrow[r]] = s * bsp[(size_t)b*N_ + idx] * mm;
            }
        }
    }
}

// ---------------- kernel 3: final reduction (single pass, shuffle-based) ----------------
__global__ void finalize_kernel(const float* __restrict__ succ,
                                const float* __restrict__ bsp,
                                float* __restrict__ out)
{
    int tid = threadIdx.x;   // 512 threads
    float a_s0 = 0.f, a_s1 = 0.f, a_s2 = 0.f, a_s3 = 0.f;
    float a_e0 = 0.f, a_e1 = 0.f, a_e2 = 0.f, a_e3 = 0.f;
    float a_g0 = 0.f, a_g1 = 0.f, a_g2v = 0.f, a_g3 = 0.f;
    float a_adds = 0.f, a_bce = 0.f;

    for (int i = tid; i < B_*N_; i += 512) {
        int b = i >> 11;
        float sv = succ[i];
        float ev = g_ew[i];
        float gv = g_contrib[i];
        if (b == 0) { a_s0 += sv; a_e0 += ev; a_g0 += gv; }
        else if (b == 1) { a_s1 += sv; a_e1 += ev; a_g1 += gv; }
        else if (b == 2) { a_s2 += sv; a_e2 += ev; a_g2v += gv; }
        else { a_s3 += sv; a_e3 += ev; a_g3 += gv; }
        float bst = g_best[i];
        float ma = isinf(bst) ? 0.0f : sqrtf(bst);
        a_adds += bsp[i] * ma;
        a_bce  += g_sbce[i];
    }

    #define WR(v) { v += __shfl_xor_sync(0xffffffffu, v, 16); \
                    v += __shfl_xor_sync(0xffffffffu, v, 8);  \
                    v += __shfl_xor_sync(0xffffffffu, v, 4);  \
                    v += __shfl_xor_sync(0xffffffffu, v, 2);  \
                    v += __shfl_xor_sync(0xffffffffu, v, 1); }
    WR(a_s0) WR(a_s1) WR(a_s2) WR(a_s3)
    WR(a_e0) WR(a_e1) WR(a_e2) WR(a_e3)
    WR(a_g0) WR(a_g1) WR(a_g2v) WR(a_g3)
    WR(a_adds) WR(a_bce)
    #undef WR

    __shared__ float red[16][14];
    int w = tid >> 5, l = tid & 31;
    if (l == 0) {
        red[w][0]=a_s0; red[w][1]=a_s1; red[w][2]=a_s2; red[w][3]=a_s3;
        red[w][4]=a_e0; red[w][5]=a_e1; red[w][6]=a_e2; red[w][7]=a_e3;
        red[w][8]=a_g0; red[w][9]=a_g1; red[w][10]=a_g2v; red[w][11]=a_g3;
        red[w][12]=a_adds; red[w][13]=a_bce;
    }
    __syncthreads();
    if (tid == 0) {
        float acc[14];
        #pragma unroll
        for (int k = 0; k < 14; k++) {
            float s = 0.f;
            for (int w2 = 0; w2 < 16; w2++) s += red[w2][k];
            acc[k] = s;
        }
        float t = 0.f;
        #pragma unroll
        for (int b = 0; b < B_; b++) {
            float piv = fmaxf(acc[b], 1.0f);
            t += (acc[4+b] + acc[8+b]) / piv;
        }
        t *= (1.0f / B_);
        t += 10.0f * acc[12] * (1.0f / (B_ * N_));
        t += acc[13] * (1.0f / (B_ * N_));
        out[0] = t;
    }
}

// ---------------- launch ----------------
extern "C" void kernel_launch(void* const* d_in, const int* in_sizes, int n_in,
                              void* d_out, int out_size)
{
    const float* gd   = (const float*)d_in[0];   // grasp_dir_head
    const float* ad   = (const float*)d_in[1];   // approach_dir_head
    const float* goh  = (const float*)d_in[2];   // grasp_offset_head
    const float* pp   = (const float*)d_in[3];   // pred_points
    const float* bsp  = (const float*)d_in[4];   // binary_score_pred
    const float* bsh  = (const float*)d_in[5];   // binary_score_head
    const float* dl   = (const float*)d_in[6];   // dir_labels_pc_cam
    const float* ol   = (const float*)d_in[7];   // offset_labels_pc
    const float* succ = (const float*)d_in[8];   // grasp_success_labels_pc
    const float* al   = (const float*)d_in[9];   // approach_labels_pc_cam
    const float* bv   = (const float*)d_in[10];  // bin_vals
    const float* bw   = (const float*)d_in[11];  // bin_weights
    const float* cp   = (const float*)d_in[12];  // control_pts
    float* out = (float*)d_out;

    prep_kernel<<<(B_*N_ + 255) / 256, 256>>>(gd, ad, goh, pp, bsh, dl, ol, succ, al, bv, bw, cp);
    dim3 grid2(N_ / (32*NT), B_, 2);
    pair_kernel<<<grid2, 256>>>(succ, bsp);
    finalize_kernel<<<1, 512>>>(succ, bsp, out);
}

// round 3
// speedup vs baseline: 6.1632x; 2.0489x over previous
#include <cuda_runtime.h>
#include <math.h>

#define B_ 4
#define N_ 2048
#define NB_ 10
#define P_ 5
#define CPD 16   // 15 dims + ||row||^2 in slot 15
#define CH 128   // streamed points per smem tile (== 32*NT)
#define NT 4     // fixed rows per thread
#define NRED 16  // partial-reduce blocks

// ---------------- scratch (no allocations allowed) ----------------
__device__ float g_pred_cp[B_*N_*CPD];
__device__ float g_gt_cp  [B_*N_*CPD];
__device__ float g_gt_c   [B_*N_*CPD];   // compacted succ gt rows (+pad)
__device__ int   g_cidx   [B_*N_];       // compact slot -> original index
__device__ int   g_nch    [B_];          // padded chunk count per batch
__device__ unsigned           g_best_u[B_*N_];  // pred->gt min (uint-ordered float)
__device__ unsigned long long g_k1[B_*N_];      // gt->pred packed (val,idx), normal
__device__ unsigned long long g_k2[B_*N_];      // gt->pred packed (val,idx), sym
__device__ float g_ew  [B_*N_];   // succ*(cos_d + cos_a + off)
__device__ float g_sbce[B_*N_];   // score bce per point
__device__ float g_part[NRED][5]; // per-block partials: s, ew, g2p, adds, bce

typedef unsigned long long ull;

__device__ __forceinline__ ull pack2(float lo, float hi) {
    ull r; asm("mov.b64 %0,{%1,%2};" : "=l"(r) : "f"(lo), "f"(hi)); return r;
}
__device__ __forceinline__ void unpack2(ull v, float& lo, float& hi) {
    asm("mov.b64 {%0,%1},%2;" : "=f"(lo), "=f"(hi) : "l"(v));
}
__device__ __forceinline__ ull fma2(ull a, ull b, ull c) {
    ull d; asm("fma.rn.f32x2 %0,%1,%2,%3;" : "=l"(d) : "l"(a), "l"(b), "l"(c)); return d;
}
__device__ __forceinline__ ull mul2(ull a, ull b) {
    ull d; asm("mul.rn.f32x2 %0,%1,%2;" : "=l"(d) : "l"(a), "l"(b)); return d;
}
__device__ __forceinline__ ull add2(ull a, ull b) {
    ull d; asm("add.rn.f32x2 %0,%1,%2;" : "=l"(d) : "l"(a), "l"(b)); return d;
}
__device__ __forceinline__ float softplusf(float x) {
    return fmaxf(x, 0.0f) + log1pf(expf(-fabsf(x)));
}
#define F_INF __int_as_float(0x7f800000)

// ---------------- kernel 1: build control points + elementwise + init ----------------
__global__ void prep_kernel(
    const float* __restrict__ gd, const float* __restrict__ ad,
    const float* __restrict__ goh, const float* __restrict__ pp,
    const float* __restrict__ bsh, const float* __restrict__ dl,
    const float* __restrict__ ol, const float* __restrict__ succ,
    const float* __restrict__ al, const float* __restrict__ bv,
    const float* __restrict__ bw, const float* __restrict__ cp)
{
    int i = blockIdx.x * blockDim.x + threadIdx.x;
    if (i >= B_ * N_) return;

    // init reduction targets (graph-replay safe: re-done every launch)
    g_best_u[i] = 0x7f800000u;
    g_k1[i] = 0xFFFFFFFFFFFFFFFFull;
    g_k2[i] = 0xFFFFFFFFFFFFFFFFull;

    float bx = gd[i*3+0], by = gd[i*3+1], bz = gd[i*3+2];
    float ax = ad[i*3+0], ay = ad[i*3+1], az = ad[i*3+2];
    float px = pp[i*3+0], py = pp[i*3+1], pz = pp[i*3+2];

    int kp = 0; float xm = goh[i*NB_];
    #pragma unroll
    for (int k = 1; k < NB_; k++) { float v = goh[i*NB_+k]; if (v > xm) { xm = v; kp = k; } }
    float thp = bv[kp];

    int kg = 0; float ym = ol[i*NB_];
    #pragma unroll
    for (int k = 1; k < NB_; k++) { float v = ol[i*NB_+k]; if (v > ym) { ym = v; kg = k; } }
    float thg = bv[kg];

    float cx = ay*bz - az*by, cy = az*bx - ax*bz, cz = ax*by - ay*bx;
    float tx = px + 0.5f*thp*bx, ty = py + 0.5f*thp*by, tz = pz + 0.5f*thp*bz;
    {
        float row[16]; float nrm = 0.0f;
        #pragma unroll
        for (int p = 0; p < P_; p++) {
            float c0 = cp[p*3+0], c1 = cp[p*3+1], c2 = cp[p*3+2];
            float vx = bx*c0 + cx*c1 + ax*c2 + tx;
            float vy = by*c0 + cy*c1 + ay*c2 + ty;
            float vz = bz*c0 + cz*c1 + az*c2 + tz;
            row[p*3+0] = vx; row[p*3+1] = vy; row[p*3+2] = vz;
            nrm += vx*vx + vy*vy + vz*vz;
        }
        row[15] = nrm;
        float4* po = (float4*)(g_pred_cp + (size_t)i * CPD);
        #pragma unroll
        for (int q = 0; q < 4; q++) po[q] = make_float4(row[q*4], row[q*4+1], row[q*4+2], row[q*4+3]);
    }

    float gbx = dl[i*3+0], gby = dl[i*3+1], gbz = dl[i*3+2];
    float gax = al[i*3+0], gay = al[i*3+1], gaz = al[i*3+2];
    float gcx = gay*gbz - gaz*gby, gcy = gaz*gbx - gax*gbz, gcz = gax*gby - gay*gbx;
    float gtx = px + 0.5f*thg*gbx, gty = py + 0.5f*thg*gby, gtz = pz + 0.5f*thg*gbz;
    {
        float row[16]; float nrm = 0.0f;
        #pragma unroll
        for (int p = 0; p < P_; p++) {
            float c0 = cp[p*3+0], c1 = cp[p*3+1], c2 = cp[p*3+2];
            float vx = gbx*c0 + gcx*c1 + gax*c2 + gtx;
            float vy = gby*c0 + gcy*c1 + gay*c2 + gty;
            float vz = gbz*c0 + gcz*c1 + gaz*c2 + gtz;
            row[p*3+0] = vx; row[p*3+1] = vy; row[p*3+2] = vz;
            nrm += vx*vx + vy*vy + vz*vz;
        }
        row[15] = nrm;
        float4* go = (float4*)(g_gt_cp + (size_t)i * CPD);
        #pragma unroll
        for (int q = 0; q < 4; q++) go[q] = make_float4(row[q*4], row[q*4+1], row[q*4+2], row[q*4+3]);
    }

    float s = succ[i];
    float cos_d = 1.0f - (gbx*bx + gby*by + gbz*bz);
    float proj = bx*gax + by*gay + bz*gaz;
    float ox = gax - proj*bx, oy = gay - proj*by, oz = gaz - proj*bz;
    float on = sqrtf(ox*ox + oy*oy + oz*oz);
    float inv = 1.0f / fmaxf(on, 1e-12f);
    float cos_a = 1.0f - (ox*ax + oy*ay + oz*az) * inv;

    float off = 0.0f;
    #pragma unroll
    for (int k = 0; k < NB_; k++) {
        float x = goh[i*NB_+k], y = ol[i*NB_+k];
        off += bw[k] * (y * softplusf(-x) + (1.0f - y) * softplusf(x));
    }
    off *= (1.0f / NB_);

    g_ew[i] = s * (cos_d + cos_a + off);
    float h = bsh[i];
    g_sbce[i] = s * softplusf(-h) + (1.0f - s) * softplusf(h);
}

// ---------------- kernel 1b: compact succ gt rows (per-batch scan) ----------------
__global__ void compact_kernel(const float* __restrict__ succ)
{
    int b = blockIdx.x;
    int tid = threadIdx.x;                 // 1024 threads, 2 elems each
    int i0 = 2*tid, i1 = 2*tid + 1;
    int f0 = succ[(size_t)b*N_ + i0] > 0.5f;
    int f1 = succ[(size_t)b*N_ + i1] > 0.5f;
    int sum = f0 + f1;

    int lane = tid & 31, w = tid >> 5;
    int v = sum;
    #pragma unroll
    for (int o = 1; o < 32; o <<= 1) {
        int u = __shfl_up_sync(0xffffffffu, v, o);
        if (lane >= o) v += u;
    }
    __shared__ int wtot[32];
    if (lane == 31) wtot[w] = v;
    __syncthreads();
    if (w == 0) {
        int t = wtot[lane];
        #pragma unroll
        for (int o = 1; o < 32; o <<= 1) {
            int u = __shfl_up_sync(0xffffffffu, t, o);
            if (lane >= o) t += u;
        }
        wtot[lane] = t;
    }
    __syncthreads();
    int excl = v - sum + (w > 0 ? wtot[w-1] : 0);

    const float4* src;
    float4* dst;
    if (f0) {
        src = (const float4*)(g_gt_cp + ((size_t)b*N_ + i0) * CPD);
        dst = (float4*)(g_gt_c + ((size_t)b*N_ + excl) * CPD);
        dst[0] = src[0]; dst[1] = src[1]; dst[2] = src[2]; dst[3] = src[3];
        g_cidx[(size_t)b*N_ + excl] = i0;
    }
    if (f1) {
        int p = excl + f0;
        src = (const float4*)(g_gt_cp + ((size_t)b*N_ + i1) * CPD);
        dst = (float4*)(g_gt_c + ((size_t)b*N_ + p) * CPD);
        dst[0] = src[0]; dst[1] = src[1]; dst[2] = src[2]; dst[3] = src[3];
        g_cidx[(size_t)b*N_ + p] = i1;
    }

    int cnt = wtot[31];
    int pad = (cnt + CH - 1) / CH * CH;
    for (int p = cnt + tid; p < pad; p += 1024) {
        float4* d = (float4*)(g_gt_c + ((size_t)b*N_ + p) * CPD);
        d[0] = make_float4(0,0,0,0);
        d[1] = make_float4(0,0,0,0);
        d[2] = make_float4(0,0,0,0);
        d[3] = make_float4(0,0,0,F_INF);   // ||row||^2 = INF -> never wins a min
        g_cidx[(size_t)b*N_ + p] = 0;      // harmless: its key is INF-valued
    }
    if (tid == 0) g_nch[b] = pad / CH;
}

// ---------------- kernel 2: pairwise, both directions, stream split 2-way ----------------
// grid (16, B_, 4): z&1 = stream half (interleaved chunks), z>>1 = direction.
// dir A (z<2): fixed = pred rows (all), streamed = compacted gt -> masked min.
// dir B (z>=2): fixed = compacted gt rows, streamed = pred (all) -> argmin keys.
// d1 = ||f||^2 + ||s||^2 - 2 f.s ; d2 = d1 + 2*dot(Delta_f, Delta_s),
//   Delta = (x6-x9, x7-x10, x8-x11)  [sym control pts = swap of points 2<->3].
__global__ __launch_bounds__(256, 2) void pair_kernel(const float* __restrict__ bsp)
{
    __shared__ float4 sg[CH*5];            // stride-5 padding: conflict-free
    int b    = blockIdx.y;
    int z    = blockIdx.z;
    int half = z & 1;
    int tid  = threadIdx.x;
    int ns   = tid >> 3;
    int ml   = tid & 7;

    if (z < 2) {
        // ---------------- direction A: pred -> compacted gt, masked min ----------------
        ull FP[NT][7];
        float f14[NT], fn[NT], fD0[NT], fD1[NT], fD2[NT];
        int nrow[NT];
        #pragma unroll
        for (int r = 0; r < NT; r++) {
            int n = blockIdx.x * (32*NT) + r*32 + ns;
            nrow[r] = n;
            const float4* row = (const float4*)(g_pred_cp + ((size_t)b*N_ + n) * CPD);
            float4 a0 = row[0], a1 = row[1], a2 = row[2], a3 = row[3];
            FP[r][0] = pack2(a0.x, a0.y); FP[r][1] = pack2(a0.z, a0.w);
            FP[r][2] = pack2(a1.x, a1.y); FP[r][3] = pack2(a1.z, a1.w);
            FP[r][4] = pack2(a2.x, a2.y); FP[r][5] = pack2(a2.z, a2.w);
            FP[r][6] = pack2(a3.x, a3.y);
            f14[r] = a3.z; fn[r] = a3.w;
            fD0[r] = a1.z - a2.y; fD1[r] = a1.w - a2.z; fD2[r] = a2.x - a2.w;
        }
        float minv[NT];
        #pragma unroll
        for (int r = 0; r < NT; r++) minv[r] = F_INF;

        int nch = g_nch[b];
        for (int c = half; c < nch; c += 2) {
            int mc = c * CH;
            __syncthreads();
            const float4* src = (const float4*)(g_gt_c + ((size_t)b*N_ + mc) * CPD);
            #pragma unroll
            for (int j = tid; j < CH*4; j += 256) sg[(j >> 2) * 5 + (j & 3)] = src[j];
            __syncthreads();

            #pragma unroll 2
            for (int j = 0; j < CH/8; j++) {
                int m = ml + j*8;
                const float4* sp = &sg[m*5];
                float4 s0 = sp[0], s1 = sp[1], s2 = sp[2], s3 = sp[3];
                ull S0 = pack2(s0.x, s0.y), S1 = pack2(s0.z, s0.w);
                ull S2 = pack2(s1.x, s1.y), S3 = pack2(s1.z, s1.w);
                ull S4 = pack2(s2.x, s2.y), S5 = pack2(s2.z, s2.w);
                ull S6 = pack2(s3.x, s3.y);
                float s14 = s3.z, sn = s3.w;
                float D0 = s1.z - s2.y, D1 = s1.w - s2.z, D2 = s2.x - s2.w;

                #pragma unroll
                for (int r = 0; r < NT; r++) {
                    ull a = mul2(FP[r][0], S0);
                    ull cc = mul2(FP[r][1], S1);
                    a = fma2(FP[r][2], S2, a);
                    cc = fma2(FP[r][3], S3, cc);
                    a = fma2(FP[r][4], S4, a);
                    cc = fma2(FP[r][5], S5, cc);
                    a = fma2(FP[r][6], S6, a);
                    a = add2(a, cc);
                    float lo, hi; unpack2(a, lo, hi);
                    float dot = fmaf(f14[r], s14, lo + hi);
                    float d1 = fmaf(-2.0f, dot, fn[r] + sn);
                    float corr = fD0[r] * D0;
                    corr = fmaf(fD1[r], D1, corr);
                    corr = fmaf(fD2[r], D2, corr);
                    float d2 = fmaf(2.0f, corr, d1);
                    float dm = fminf(fmaxf(d1, 0.0f), fmaxf(d2, 0.0f));
                    minv[r] = fminf(minv[r], dm);
                }
            }
        }
        #pragma unroll
        for (int r = 0; r < NT; r++) {
            float v = minv[r];
            v = fminf(v, __shfl_down_sync(0xffffffffu, v, 4));
            v = fminf(v, __shfl_down_sync(0xffffffffu, v, 2));
            v = fminf(v, __shfl_down_sync(0xffffffffu, v, 1));
            if (ml == 0)
                atomicMin(&g_best_u[(size_t)b*N_ + nrow[r]], __float_as_uint(v));
        }
    } else {
        // ---------------- direction B: compacted gt -> pred, argmin keys ----------------
        int padcnt = g_nch[b] * CH;
        int row0 = blockIdx.x * (32*NT);
        if (row0 >= padcnt) return;

        ull FP[NT][7];
        float f14[NT], fn[NT], fD0[NT], fD1[NT], fD2[NT];
        int orig[NT];
        #pragma unroll
        for (int r = 0; r < NT; r++) {
            int n = row0 + r*32 + ns;
            orig[r] = g_cidx[(size_t)b*N_ + n];
            const float4* row = (const float4*)(g_gt_c + ((size_t)b*N_ + n) * CPD);
            float4 a0 = row[0], a1 = row[1], a2 = row[2], a3 = row[3];
            FP[r][0] = pack2(a0.x, a0.y); FP[r][1] = pack2(a0.z, a0.w);
            FP[r][2] = pack2(a1.x, a1.y); FP[r][3] = pack2(a1.z, a1.w);
            FP[r][4] = pack2(a2.x, a2.y); FP[r][5] = pack2(a2.z, a2.w);
            FP[r][6] = pack2(a3.x, a3.y);
            f14[r] = a3.z; fn[r] = a3.w;
            fD0[r] = a1.z - a2.y; fD1[r] = a1.w - a2.z; fD2[r] = a2.x - a2.w;
        }
        ull b1[NT], b2[NT];
        #pragma unroll
        for (int r = 0; r < NT; r++) { b1[r] = ~0ull; b2[r] = ~0ull; }

        for (int c = half; c < N_/CH; c += 2) {
            int mc = c * CH;
            __syncthreads();
            const float4* src = (const float4*)(g_pred_cp + ((size_t)b*N_ + mc) * CPD);
            #pragma unroll
            for (int j = tid; j < CH*4; j += 256) sg[(j >> 2) * 5 + (j & 3)] = src[j];
            __syncthreads();

            #pragma unroll 2
            for (int j = 0; j < CH/8; j++) {
                int m = ml + j*8;
                const float4* sp = &sg[m*5];
                float4 s0 = sp[0], s1 = sp[1], s2 = sp[2], s3 = sp[3];
                ull S0 = pack2(s0.x, s0.y), S1 = pack2(s0.z, s0.w);
                ull S2 = pack2(s1.x, s1.y), S3 = pack2(s1.z, s1.w);
                ull S4 = pack2(s2.x, s2.y), S5 = pack2(s2.z, s2.w);
                ull S6 = pack2(s3.x, s3.y);
                float s14 = s3.z, sn = s3.w;
                float D0 = s1.z - s2.y, D1 = s1.w - s2.z, D2 = s2.x - s2.w;
                unsigned idx = (unsigned)(mc + m);

                #pragma unroll
                for (int r = 0; r < NT; r++) {
                    ull a = mul2(FP[r][0], S0);
                    ull cc = mul2(FP[r][1], S1);
                    a = fma2(FP[r][2], S2, a);
                    cc = fma2(FP[r][3], S3, cc);
                    a = fma2(FP[r][4], S4, a);
                    cc = fma2(FP[r][5], S5, cc);
                    a = fma2(FP[r][6], S6, a);
                    a = add2(a, cc);
                    float lo, hi; unpack2(a, lo, hi);
                    float dot = fmaf(f14[r], s14, lo + hi);
                    float d1 = fmaf(-2.0f, dot, fn[r] + sn);
                    float corr = fD0[r] * D0;
                    corr = fmaf(fD1[r], D1, corr);
                    corr = fmaf(fD2[r], D2, corr);
                    float d2 = fmaf(2.0f, corr, d1);
                    d1 = fmaxf(d1, 0.0f);
                    d2 = fmaxf(d2, 0.0f);
                    ull k1 = ((ull)__float_as_uint(d1) << 32) | idx;
                    ull k2 = ((ull)__float_as_uint(d2) << 32) | idx;
                    if (k1 < b1[r]) b1[r] = k1;
                    if (k2 < b2[r]) b2[r] = k2;
                }
            }
        }
        #pragma unroll
        for (int r = 0; r < NT; r++) {
            ull v1 = b1[r], v2 = b2[r], o;
            o = __shfl_down_sync(0xffffffffu, v1, 4); if (o < v1) v1 = o;
            o = __shfl_down_sync(0xffffffffu, v1, 2); if (o < v1) v1 = o;
            o = __shfl_down_sync(0xffffffffu, v1, 1); if (o < v1) v1 = o;
            o = __shfl_down_sync(0xffffffffu, v2, 4); if (o < v2) v2 = o;
            o = __shfl_down_sync(0xffffffffu, v2, 2); if (o < v2) v2 = o;
            o = __shfl_down_sync(0xffffffffu, v2, 1); if (o < v2) v2 = o;
            if (ml == 0) {
                atomicMin(&g_k1[(size_t)b*N_ + orig[r]], v1);
                atomicMin(&g_k2[(size_t)b*N_ + orig[r]], v2);
            }
        }
    }
}

// ---------------- kernel 3a: partial reduce (16 blocks x 512, 1 elem/thread) ----------------
__global__ void reduce1_kernel(const float* __restrict__ succ,
                               const float* __restrict__ bsp)
{
    int i = blockIdx.x * 512 + threadIdx.x;
    int b = i >> 11;
    float sv = succ[i];
    float ev = g_ew[i];

    float gv = 0.0f;
    if (sv > 0.5f) {
        ull k1 = g_k1[i], k2 = g_k2[i];
        float m1 = __uint_as_float((unsigned)(k1 >> 32));
        float m2 = __uint_as_float((unsigned)(k2 >> 32));
        int i1 = (int)(k1 & 0xFFFFFFFFu);
        int i2 = (int)(k2 & 0xFFFFFFFFu);
        int idx = (m2 < m1) ? i2 : i1;
        gv = sv * bsp[(size_t)b*N_ + idx] * fminf(m1, m2);
    }

    unsigned bu = g_best_u[i];
    float ma = (bu == 0x7f800000u) ? 0.0f : sqrtf(__uint_as_float(bu));
    float av = bsp[i] * ma;
    float cv = g_sbce[i];

    // block reduce 5 values
    #define WR(v) { v += __shfl_xor_sync(0xffffffffu, v, 16); \
                    v += __shfl_xor_sync(0xffffffffu, v, 8);  \
                    v += __shfl_xor_sync(0xffffffffu, v, 4);  \
                    v += __shfl_xor_sync(0xffffffffu, v, 2);  \
                    v += __shfl_xor_sync(0xffffffffu, v, 1); }
    WR(sv) WR(ev) WR(gv) WR(av) WR(cv)
    #undef WR

    __shared__ float red[16][5];
    int w = threadIdx.x >> 5, l = threadIdx.x & 31;
    if (l == 0) { red[w][0]=sv; red[w][1]=ev; red[w][2]=gv; red[w][3]=av; red[w][4]=cv; }
    __syncthreads();
    if (threadIdx.x == 0) {
        float a0=0,a1=0,a2=0,a3=0,a4=0;
        #pragma unroll
        for (int k = 0; k < 16; k++) {
            a0+=red[k][0]; a1+=red[k][1]; a2+=red[k][2]; a3+=red[k][3]; a4+=red[k][4];
        }
        g_part[blockIdx.x][0]=a0; g_part[blockIdx.x][1]=a1; g_part[blockIdx.x][2]=a2;
        g_part[blockIdx.x][3]=a3; g_part[blockIdx.x][4]=a4;
    }
}

// ---------------- kernel 3b: combine (1 warp) ----------------
__global__ void reduce2_kernel(float* __restrict__ out)
{
    int t = threadIdx.x;  // 32 threads, first 16 carry data
    float s = 0, e = 0, g = 0, ad = 0, bc = 0;
    if (t < NRED) {
        s = g_part[t][0]; e = g_part[t][1]; g = g_part[t][2];
        ad = g_part[t][3]; bc = g_part[t][4];
    }
    // per-batch (groups of 4 consecutive blocks)
    s += __shfl_xor_sync(0xffffffffu, s, 1); s += __shfl_xor_sync(0xffffffffu, s, 2);
    e += __shfl_xor_sync(0xffffffffu, e, 1); e += __shfl_xor_sync(0xffffffffu, e, 2);
    g += __shfl_xor_sync(0xffffffffu, g, 1); g += __shfl_xor_sync(0xffffffffu, g, 2);
    // global
    ad += __shfl_xor_sync(0xffffffffu, ad, 1); ad += __shfl_xor_sync(0xffffffffu, ad, 2);
    ad += __shfl_xor_sync(0xffffffffu, ad, 4); ad += __shfl_xor_sync(0xffffffffu, ad, 8);
    bc += __shfl_xor_sync(0xffffffffu, bc, 1); bc += __shfl_xor_sync(0xffffffffu, bc, 2);
    bc += __shfl_xor_sync(0xffffffffu, bc, 4); bc += __shfl_xor_sync(0xffffffffu, bc, 8);

    float S0 = __shfl_sync(0xffffffffu, s, 0),  E0 = __shfl_sync(0xffffffffu, e, 0),  G0 = __shfl_sync(0xffffffffu, g, 0);
    float S1 = __shfl_sync(0xffffffffu, s, 4),  E1 = __shfl_sync(0xffffffffu, e, 4),  G1 = __shfl_sync(0xffffffffu, g, 4);
    float S2 = __shfl_sync(0xffffffffu, s, 8),  E2 = __shfl_sync(0xffffffffu, e, 8),  G2 = __shfl_sync(0xffffffffu, g, 8);
    float S3 = __shfl_sync(0xffffffffu, s, 12), E3 = __shfl_sync(0xffffffffu, e, 12), G3 = __shfl_sync(0xffffffffu, g, 12);
    float AD = __shfl_sync(0xffffffffu, ad, 0);
    float BC = __shfl_sync(0xffffffffu, bc, 0);

    if (t == 0) {
        float tot = (E0 + G0) / fmaxf(S0, 1.0f)
                  + (E1 + G1) / fmaxf(S1, 1.0f)
                  + (E2 + G2) / fmaxf(S2, 1.0f)
                  + (E3 + G3) / fmaxf(S3, 1.0f);
        tot *= (1.0f / B_);
        tot += 10.0f * AD * (1.0f / (B_ * N_));
        tot += BC * (1.0f / (B_ * N_));
        out[0] = tot;
    }
}

// ---------------- launch ----------------
extern "C" void kernel_launch(void* const* d_in, const int* in_sizes, int n_in,
                              void* d_out, int out_size)
{
    const float* gd   = (const float*)d_in[0];
    const float* ad   = (const float*)d_in[1];
    const float* goh  = (const float*)d_in[2];
    const float* pp   = (const float*)d_in[3];
    const float* bsp  = (const float*)d_in[4];
    const float* bsh  = (const float*)d_in[5];
    const float* dl   = (const float*)d_in[6];
    const float* ol   = (const float*)d_in[7];
    const float* succ = (const float*)d_in[8];
    const float* al   = (const float*)d_in[9];
    const float* bv   = (const float*)d_in[10];
    const float* bw   = (const float*)d_in[11];
    const float* cp   = (const float*)d_in[12];
    float* out = (float*)d_out;

    prep_kernel<<<(B_*N_ + 127) / 128, 128>>>(gd, ad, goh, pp, bsh, dl, ol, succ, al, bv, bw, cp);
    compact_kernel<<<B_, 1024>>>(succ);
    dim3 grid2(N_ / (32*NT), B_, 4);
    pair_kernel<<<grid2, 256>>>(bsp);
    reduce1_kernel<<<NRED, 512>>>(succ, bsp);
    reduce2_kernel<<<1, 32>>>(out);
}

// round 4
// speedup vs baseline: 8.6498x; 1.4035x over previous
#include <cuda_runtime.h>
#include <math.h>

#define B_ 4
#define N_ 2048
#define NB_ 10
#define P_ 5
#define CPD 16   // 15 dims + ||row||^2 in slot 15
#define CH 128   // streamed points per smem tile (== 32*NT)
#define NT 4     // fixed rows per thread

// ---------------- scratch (no allocations allowed) ----------------
__device__ float g_pred_cp[B_*N_*CPD];
__device__ float g_gt_cp  [B_*N_*CPD];
__device__ float g_gt_c   [B_*N_*CPD];   // compacted succ gt rows (+pad)
__device__ int   g_cidx   [B_*N_];       // compact slot -> original index
__device__ int   g_nch    [B_];          // padded chunk count per batch
__device__ unsigned           g_best_u[B_*N_];  // pred->gt min (uint-ordered float)
__device__ unsigned long long g_k1[B_*N_];      // gt->pred packed (val,idx), normal
__device__ unsigned long long g_k2[B_*N_];      // gt->pred packed (val,idx), sym
__device__ float g_ew  [B_*N_];   // succ*(cos_d + cos_a + off)
__device__ float g_sbce[B_*N_];   // score bce per point

typedef unsigned long long ull;

__device__ __forceinline__ ull pack2(float lo, float hi) {
    ull r; asm("mov.b64 %0,{%1,%2};" : "=l"(r) : "f"(lo), "f"(hi)); return r;
}
__device__ __forceinline__ void unpack2(ull v, float& lo, float& hi) {
    asm("mov.b64 {%0,%1},%2;" : "=f"(lo), "=f"(hi) : "l"(v));
}
__device__ __forceinline__ ull fma2(ull a, ull b, ull c) {
    ull d; asm("fma.rn.f32x2 %0,%1,%2,%3;" : "=l"(d) : "l"(a), "l"(b), "l"(c)); return d;
}
__device__ __forceinline__ ull mul2(ull a, ull b) {
    ull d; asm("mul.rn.f32x2 %0,%1,%2;" : "=l"(d) : "l"(a), "l"(b)); return d;
}
__device__ __forceinline__ ull add2(ull a, ull b) {
    ull d; asm("add.rn.f32x2 %0,%1,%2;" : "=l"(d) : "l"(a), "l"(b)); return d;
}
__device__ __forceinline__ float softplusf(float x) {
    return fmaxf(x, 0.0f) + log1pf(expf(-fabsf(x)));
}
#define F_INF __int_as_float(0x7f800000)

// ---------------- kernel 1: build control points + elementwise + init ----------------
__global__ void prep_kernel(
    const float* __restrict__ gd, const float* __restrict__ ad,
    const float* __restrict__ goh, const float* __restrict__ pp,
    const float* __restrict__ bsh, const float* __restrict__ dl,
    const float* __restrict__ ol, const float* __restrict__ succ,
    const float* __restrict__ al, const float* __restrict__ bv,
    const float* __restrict__ bw, const float* __restrict__ cp)
{
    int i = blockIdx.x * blockDim.x + threadIdx.x;
    if (i >= B_ * N_) return;

    g_best_u[i] = 0x7f800000u;
    g_k1[i] = 0xFFFFFFFFFFFFFFFFull;
    g_k2[i] = 0xFFFFFFFFFFFFFFFFull;

    float bx = gd[i*3+0], by = gd[i*3+1], bz = gd[i*3+2];
    float ax = ad[i*3+0], ay = ad[i*3+1], az = ad[i*3+2];
    float px = pp[i*3+0], py = pp[i*3+1], pz = pp[i*3+2];

    int kp = 0; float xm = goh[i*NB_];
    #pragma unroll
    for (int k = 1; k < NB_; k++) { float v = goh[i*NB_+k]; if (v > xm) { xm = v; kp = k; } }
    float thp = bv[kp];

    int kg = 0; float ym = ol[i*NB_];
    #pragma unroll
    for (int k = 1; k < NB_; k++) { float v = ol[i*NB_+k]; if (v > ym) { ym = v; kg = k; } }
    float thg = bv[kg];

    float cx = ay*bz - az*by, cy = az*bx - ax*bz, cz = ax*by - ay*bx;
    float tx = px + 0.5f*thp*bx, ty = py + 0.5f*thp*by, tz = pz + 0.5f*thp*bz;
    {
        float row[16]; float nrm = 0.0f;
        #pragma unroll
        for (int p = 0; p < P_; p++) {
            float c0 = cp[p*3+0], c1 = cp[p*3+1], c2 = cp[p*3+2];
            float vx = bx*c0 + cx*c1 + ax*c2 + tx;
            float vy = by*c0 + cy*c1 + ay*c2 + ty;
            float vz = bz*c0 + cz*c1 + az*c2 + tz;
            row[p*3+0] = vx; row[p*3+1] = vy; row[p*3+2] = vz;
            nrm += vx*vx + vy*vy + vz*vz;
        }
        row[15] = nrm;
        float4* po = (float4*)(g_pred_cp + (size_t)i * CPD);
        #pragma unroll
        for (int q = 0; q < 4; q++) po[q] = make_float4(row[q*4], row[q*4+1], row[q*4+2], row[q*4+3]);
    }

    float gbx = dl[i*3+0], gby = dl[i*3+1], gbz = dl[i*3+2];
    float gax = al[i*3+0], gay = al[i*3+1], gaz = al[i*3+2];
    float gcx = gay*gbz - gaz*gby, gcy = gaz*gbx - gax*gbz, gcz = gax*gby - gay*gbx;
    float gtx = px + 0.5f*thg*gbx, gty = py + 0.5f*thg*gby, gtz = pz + 0.5f*thg*gbz;
    {
        float row[16]; float nrm = 0.0f;
        #pragma unroll
        for (int p = 0; p < P_; p++) {
            float c0 = cp[p*3+0], c1 = cp[p*3+1], c2 = cp[p*3+2];
            float vx = gbx*c0 + gcx*c1 + gax*c2 + gtx;
            float vy = gby*c0 + gcy*c1 + gay*c2 + gty;
            float vz = gbz*c0 + gcz*c1 + gaz*c2 + gtz;
            row[p*3+0] = vx; row[p*3+1] = vy; row[p*3+2] = vz;
            nrm += vx*vx + vy*vy + vz*vz;
        }
        row[15] = nrm;
        float4* go = (float4*)(g_gt_cp + (size_t)i * CPD);
        #pragma unroll
        for (int q = 0; q < 4; q++) go[q] = make_float4(row[q*4], row[q*4+1], row[q*4+2], row[q*4+3]);
    }

    float s = succ[i];
    float cos_d = 1.0f - (gbx*bx + gby*by + gbz*bz);
    float proj = bx*gax + by*gay + bz*gaz;
    float ox = gax - proj*bx, oy = gay - proj*by, oz = gaz - proj*bz;
    float on = sqrtf(ox*ox + oy*oy + oz*oz);
    float inv = 1.0f / fmaxf(on, 1e-12f);
    float cos_a = 1.0f - (ox*ax + oy*ay + oz*az) * inv;

    float off = 0.0f;
    #pragma unroll
    for (int k = 0; k < NB_; k++) {
        float x = goh[i*NB_+k], y = ol[i*NB_+k];
        off += bw[k] * (y * softplusf(-x) + (1.0f - y) * softplusf(x));
    }
    off *= (1.0f / NB_);

    g_ew[i] = s * (cos_d + cos_a + off);
    float h = bsh[i];
    g_sbce[i] = s * softplusf(-h) + (1.0f - s) * softplusf(h);
}

// ---------------- kernel 1b: compact succ gt rows (per-batch scan) ----------------
__global__ void compact_kernel(const float* __restrict__ succ)
{
    int b = blockIdx.x;
    int tid = threadIdx.x;                 // 1024 threads, 2 elems each
    int i0 = 2*tid, i1 = 2*tid + 1;
    int f0 = succ[(size_t)b*N_ + i0] > 0.5f;
    int f1 = succ[(size_t)b*N_ + i1] > 0.5f;
    int sum = f0 + f1;

    int lane = tid & 31, w = tid >> 5;
    int v = sum;
    #pragma unroll
    for (int o = 1; o < 32; o <<= 1) {
        int u = __shfl_up_sync(0xffffffffu, v, o);
        if (lane >= o) v += u;
    }
    __shared__ int wtot[32];
    if (lane == 31) wtot[w] = v;
    __syncthreads();
    if (w == 0) {
        int t = wtot[lane];
        #pragma unroll
        for (int o = 1; o < 32; o <<= 1) {
            int u = __shfl_up_sync(0xffffffffu, t, o);
            if (lane >= o) t += u;
        }
        wtot[lane] = t;
    }
    __syncthreads();
    int excl = v - sum + (w > 0 ? wtot[w-1] : 0);

    if (f0) {
        const float4* src = (const float4*)(g_gt_cp + ((size_t)b*N_ + i0) * CPD);
        float4* dst = (float4*)(g_gt_c + ((size_t)b*N_ + excl) * CPD);
        dst[0] = src[0]; dst[1] = src[1]; dst[2] = src[2]; dst[3] = src[3];
        g_cidx[(size_t)b*N_ + excl] = i0;
    }
    if (f1) {
        int p = excl + f0;
        const float4* src = (const float4*)(g_gt_cp + ((size_t)b*N_ + i1) * CPD);
        float4* dst = (float4*)(g_gt_c + ((size_t)b*N_ + p) * CPD);
        dst[0] = src[0]; dst[1] = src[1]; dst[2] = src[2]; dst[3] = src[3];
        g_cidx[(size_t)b*N_ + p] = i1;
    }

    int cnt = wtot[31];
    int pad = (cnt + CH - 1) / CH * CH;
    for (int p = cnt + tid; p < pad; p += 1024) {
        float4* d = (float4*)(g_gt_c + ((size_t)b*N_ + p) * CPD);
        d[0] = make_float4(0,0,0,0);
        d[1] = make_float4(0,0,0,0);
        d[2] = make_float4(0,0,0,0);
        d[3] = make_float4(0,0,0,F_INF);
        g_cidx[(size_t)b*N_ + p] = 0;
    }
    if (tid == 0) g_nch[b] = pad / CH;
}

// ---------------- kernel 2: pairwise, both directions, balanced splits ----------------
// grid (16, B_, 6):
//   z in {0,1}: dir A, stream-half z.   fixed = all 2048 pred rows (16 x-blocks),
//               streamed = compacted gt chunks c = z, z+2, ... -> masked min.
//   z in {2..5}: dir B, stream-quarter z-2. fixed = compacted gt rows
//               (x-blocks with row0 < padcnt; ~8 active), streamed = pred chunks
//               c = q, q+4, ... -> packed argmin keys.
// Every active block: 128 fixed rows x ~512 streamed points -> uniform makespan.
__global__ __launch_bounds__(256, 2) void pair_kernel(const float* __restrict__ bsp)
{
    __shared__ float4 sg[CH*5];            // stride-5 padding: conflict-free
    int b    = blockIdx.y;
    int z    = blockIdx.z;
    int tid  = threadIdx.x;
    int ns   = tid >> 3;
    int ml   = tid & 7;

    if (z < 2) {
        // ---------------- direction A ----------------
        int half = z;
        ull FP[NT][7];
        float f14[NT], fn[NT], fD0[NT], fD1[NT], fD2[NT];
        int nrow[NT];
        #pragma unroll
        for (int r = 0; r < NT; r++) {
            int n = blockIdx.x * (32*NT) + r*32 + ns;
            nrow[r] = n;
            const float4* row = (const float4*)(g_pred_cp + ((size_t)b*N_ + n) * CPD);
            float4 a0 = row[0], a1 = row[1], a2 = row[2], a3 = row[3];
            FP[r][0] = pack2(a0.x, a0.y); FP[r][1] = pack2(a0.z, a0.w);
            FP[r][2] = pack2(a1.x, a1.y); FP[r][3] = pack2(a1.z, a1.w);
            FP[r][4] = pack2(a2.x, a2.y); FP[r][5] = pack2(a2.z, a2.w);
            FP[r][6] = pack2(a3.x, a3.y);
            f14[r] = a3.z; fn[r] = a3.w;
            fD0[r] = a1.z - a2.y; fD1[r] = a1.w - a2.z; fD2[r] = a2.x - a2.w;
        }
        float minv[NT];
        #pragma unroll
        for (int r = 0; r < NT; r++) minv[r] = F_INF;

        int nch = g_nch[b];
        for (int c = half; c < nch; c += 2) {
            int mc = c * CH;
            __syncthreads();
            const float4* src = (const float4*)(g_gt_c + ((size_t)b*N_ + mc) * CPD);
            #pragma unroll
            for (int j = tid; j < CH*4; j += 256) sg[(j >> 2) * 5 + (j & 3)] = src[j];
            __syncthreads();

            #pragma unroll 2
            for (int j = 0; j < CH/8; j++) {
                int m = ml + j*8;
                const float4* sp = &sg[m*5];
                float4 s0 = sp[0], s1 = sp[1], s2 = sp[2], s3 = sp[3];
                ull S0 = pack2(s0.x, s0.y), S1 = pack2(s0.z, s0.w);
                ull S2 = pack2(s1.x, s1.y), S3 = pack2(s1.z, s1.w);
                ull S4 = pack2(s2.x, s2.y), S5 = pack2(s2.z, s2.w);
                ull S6 = pack2(s3.x, s3.y);
                float s14 = s3.z, sn = s3.w;
                float D0 = s1.z - s2.y, D1 = s1.w - s2.z, D2 = s2.x - s2.w;

                #pragma unroll
                for (int r = 0; r < NT; r++) {
                    ull a = mul2(FP[r][0], S0);
                    ull cc = mul2(FP[r][1], S1);
                    a = fma2(FP[r][2], S2, a);
                    cc = fma2(FP[r][3], S3, cc);
                    a = fma2(FP[r][4], S4, a);
                    cc = fma2(FP[r][5], S5, cc);
                    a = fma2(FP[r][6], S6, a);
                    a = add2(a, cc);
                    float lo, hi; unpack2(a, lo, hi);
                    float dot = fmaf(f14[r], s14, lo + hi);
                    float d1 = fmaf(-2.0f, dot, fn[r] + sn);
                    float corr = fD0[r] * D0;
                    corr = fmaf(fD1[r], D1, corr);
                    corr = fmaf(fD2[r], D2, corr);
                    float d2 = fmaf(2.0f, corr, d1);
                    float dm = fminf(fmaxf(d1, 0.0f), fmaxf(d2, 0.0f));
                    minv[r] = fminf(minv[r], dm);
                }
            }
        }
        #pragma unroll
        for (int r = 0; r < NT; r++) {
            float v = minv[r];
            v = fminf(v, __shfl_down_sync(0xffffffffu, v, 4));
            v = fminf(v, __shfl_down_sync(0xffffffffu, v, 2));
            v = fminf(v, __shfl_down_sync(0xffffffffu, v, 1));
            if (ml == 0)
                atomicMin(&g_best_u[(size_t)b*N_ + nrow[r]], __float_as_uint(v));
        }
    } else {
        // ---------------- direction B ----------------
        int quart = z - 2;
        int padcnt = g_nch[b] * CH;
        int row0 = blockIdx.x * (32*NT);
        if (row0 >= padcnt) return;

        ull FP[NT][7];
        float f14[NT], fn[NT], fD0[NT], fD1[NT], fD2[NT];
        int orig[NT];
        #pragma unroll
        for (int r = 0; r < NT; r++) {
            int n = row0 + r*32 + ns;
            orig[r] = g_cidx[(size_t)b*N_ + n];
            const float4* row = (const float4*)(g_gt_c + ((size_t)b*N_ + n) * CPD);
            float4 a0 = row[0], a1 = row[1], a2 = row[2], a3 = row[3];
            FP[r][0] = pack2(a0.x, a0.y); FP[r][1] = pack2(a0.z, a0.w);
            FP[r][2] = pack2(a1.x, a1.y); FP[r][3] = pack2(a1.z, a1.w);
            FP[r][4] = pack2(a2.x, a2.y); FP[r][5] = pack2(a2.z, a2.w);
            FP[r][6] = pack2(a3.x, a3.y);
            f14[r] = a3.z; fn[r] = a3.w;
            fD0[r] = a1.z - a2.y; fD1[r] = a1.w - a2.z; fD2[r] = a2.x - a2.w;
        }
        ull b1[NT], b2[NT];
        #pragma unroll
        for (int r = 0; r < NT; r++) { b1[r] = ~0ull; b2[r] = ~0ull; }

        for (int c = quart; c < N_/CH; c += 4) {
            int mc = c * CH;
            __syncthreads();
            const float4* src = (const float4*)(g_pred_cp + ((size_t)b*N_ + mc) * CPD);
            #pragma unroll
            for (int j = tid; j < CH*4; j += 256) sg[(j >> 2) * 5 + (j & 3)] = src[j];
            __syncthreads();

            #pragma unroll 2
            for (int j = 0; j < CH/8; j++) {
                int m = ml + j*8;
                const float4* sp = &sg[m*5];
                float4 s0 = sp[0], s1 = sp[1], s2 = sp[2], s3 = sp[3];
                ull S0 = pack2(s0.x, s0.y), S1 = pack2(s0.z, s0.w);
                ull S2 = pack2(s1.x, s1.y), S3 = pack2(s1.z, s1.w);
                ull S4 = pack2(s2.x, s2.y), S5 = pack2(s2.z, s2.w);
                ull S6 = pack2(s3.x, s3.y);
                float s14 = s3.z, sn = s3.w;
                float D0 = s1.z - s2.y, D1 = s1.w - s2.z, D2 = s2.x - s2.w;
                unsigned idx = (unsigned)(mc + m);

                #pragma unroll
                for (int r = 0; r < NT; r++) {
                    ull a = mul2(FP[r][0], S0);
                    ull cc = mul2(FP[r][1], S1);
                    a = fma2(FP[r][2], S2, a);
                    cc = fma2(FP[r][3], S3, cc);
                    a = fma2(FP[r][4], S4, a);
                    cc = fma2(FP[r][5], S5, cc);
                    a = fma2(FP[r][6], S6, a);
                    a = add2(a, cc);
                    float lo, hi; unpack2(a, lo, hi);
                    float dot = fmaf(f14[r], s14, lo + hi);
                    float d1 = fmaf(-2.0f, dot, fn[r] + sn);
                    float corr = fD0[r] * D0;
                    corr = fmaf(fD1[r], D1, corr);
                    corr = fmaf(fD2[r], D2, corr);
                    float d2 = fmaf(2.0f, corr, d1);
                    d1 = fmaxf(d1, 0.0f);
                    d2 = fmaxf(d2, 0.0f);
                    ull k1 = ((ull)__float_as_uint(d1) << 32) | idx;
                    ull k2 = ((ull)__float_as_uint(d2) << 32) | idx;
                    if (k1 < b1[r]) b1[r] = k1;
                    if (k2 < b2[r]) b2[r] = k2;
                }
            }
        }
        #pragma unroll
        for (int r = 0; r < NT; r++) {
            ull v1 = b1[r], v2 = b2[r], o;
            o = __shfl_down_sync(0xffffffffu, v1, 4); if (o < v1) v1 = o;
            o = __shfl_down_sync(0xffffffffu, v1, 2); if (o < v1) v1 = o;
            o = __shfl_down_sync(0xffffffffu, v1, 1); if (o < v1) v1 = o;
            o = __shfl_down_sync(0xffffffffu, v2, 4); if (o < v2) v2 = o;
            o = __shfl_down_sync(0xffffffffu, v2, 2); if (o < v2) v2 = o;
            o = __shfl_down_sync(0xffffffffu, v2, 1); if (o < v2) v2 = o;
            if (ml == 0) {
                atomicMin(&g_k1[(size_t)b*N_ + orig[r]], v1);
                atomicMin(&g_k2[(size_t)b*N_ + orig[r]], v2);
            }
        }
    }
}

// ---------------- kernel 3: fused final reduction (single block) ----------------
__global__ void finalize_kernel(const float* __restrict__ succ,
                                const float* __restrict__ bsp,
                                float* __restrict__ out)
{
    int tid = threadIdx.x;  // 1024 threads, 8 elems each
    float a_s0=0,a_s1=0,a_s2=0,a_s3=0;
    float a_e0=0,a_e1=0,a_e2=0,a_e3=0;
    float a_g0=0,a_g1=0,a_g2=0,a_g3=0;
    float a_ad=0,a_bc=0;

    #pragma unroll
    for (int k = 0; k < 8; k++) {
        int i = k*1024 + tid;
        int b = i >> 11;
        float sv = succ[i];
        float ev = g_ew[i];
        float gv = 0.0f;
        if (sv > 0.5f) {
            ull k1 = g_k1[i], k2 = g_k2[i];
            float m1 = __uint_as_float((unsigned)(k1 >> 32));
            float m2 = __uint_as_float((unsigned)(k2 >> 32));
            int i1 = (int)(k1 & 0xFFFFFFFFu);
            int i2 = (int)(k2 & 0xFFFFFFFFu);
            int idx = (m2 < m1) ? i2 : i1;
            gv = sv * bsp[(size_t)b*N_ + idx] * fminf(m1, m2);
        }
        if (b == 0) { a_s0 += sv; a_e0 += ev; a_g0 += gv; }
        else if (b == 1) { a_s1 += sv; a_e1 += ev; a_g1 += gv; }
        else if (b == 2) { a_s2 += sv; a_e2 += ev; a_g2 += gv; }
        else { a_s3 += sv; a_e3 += ev; a_g3 += gv; }
        unsigned bu = g_best_u[i];
        float ma = (bu == 0x7f800000u) ? 0.0f : sqrtf(__uint_as_float(bu));
        a_ad += bsp[i] * ma;
        a_bc += g_sbce[i];
    }

    #define WR(v) { v += __shfl_xor_sync(0xffffffffu, v, 16); \
                    v += __shfl_xor_sync(0xffffffffu, v, 8);  \
                    v += __shfl_xor_sync(0xffffffffu, v, 4);  \
                    v += __shfl_xor_sync(0xffffffffu, v, 2);  \
                    v += __shfl_xor_sync(0xffffffffu, v, 1); }
    WR(a_s0) WR(a_s1) WR(a_s2) WR(a_s3)
    WR(a_e0) WR(a_e1) WR(a_e2) WR(a_e3)
    WR(a_g0) WR(a_g1) WR(a_g2) WR(a_g3)
    WR(a_ad) WR(a_bc)

    __shared__ float red[32][14];
    int w = tid >> 5, l = tid & 31;
    if (l == 0) {
        red[w][0]=a_s0; red[w][1]=a_s1; red[w][2]=a_s2; red[w][3]=a_s3;
        red[w][4]=a_e0; red[w][5]=a_e1; red[w][6]=a_e2; red[w][7]=a_e3;
        red[w][8]=a_g0; red[w][9]=a_g1; red[w][10]=a_g2; red[w][11]=a_g3;
        red[w][12]=a_ad; red[w][13]=a_bc;
    }
    __syncthreads();
    if (w == 0) {
        float acc[14];
        #pragma unroll
        for (int k = 0; k < 14; k++) {
            float v = red[l][k];
            WR(v)
            acc[k] = v;
        }
        if (l == 0) {
            float t = 0.f;
            #pragma unroll
            for (int b = 0; b < B_; b++)
                t += (acc[4+b] + acc[8+b]) / fmaxf(acc[b], 1.0f);
            t *= (1.0f / B_);
            t += 10.0f * acc[12] * (1.0f / (B_ * N_));
            t += acc[13] * (1.0f / (B_ * N_));
            out[0] = t;
        }
    }
    #undef WR
}

// ---------------- launch ----------------
extern "C" void kernel_launch(void* const* d_in, const int* in_sizes, int n_in,
                              void* d_out, int out_size)
{
    const float* gd   = (const float*)d_in[0];
    const float* ad   = (const float*)d_in[1];
    const float* goh  = (const float*)d_in[2];
    const float* pp   = (const float*)d_in[3];
    const float* bsp  = (const float*)d_in[4];
    const float* bsh  = (const float*)d_in[5];
    const float* dl   = (const float*)d_in[6];
    const float* ol   = (const float*)d_in[7];
    const float* succ = (const float*)d_in[8];
    const float* al   = (const float*)d_in[9];
    const float* bv   = (const float*)d_in[10];
    const float* bw   = (const float*)d_in[11];
    const float* cp   = (const float*)d_in[12];
    float* out = (float*)d_out;

    prep_kernel<<<(B_*N_ + 127) / 128, 128>>>(gd, ad, goh, pp, bsh, dl, ol, succ, al, bv, bw, cp);
    compact_kernel<<<B_, 1024>>>(succ);
    dim3 grid2(N_ / (32*NT), B_, 6);
    pair_kernel<<<grid2, 256>>>(bsp);
    finalize_kernel<<<1, 1024>>>(succ, bsp, out);
}

// round 5
// speedup vs baseline: 9.6321x; 1.1136x over previous
#include <cuda_runtime.h>
#include <math.h>

#define B_ 4
#define N_ 2048
#define NB_ 10
#define P_ 5
#define CPD 16   // 15 dims + ||row||^2 in slot 15
#define CH 128   // streamed points per smem tile (== 32*NT)
#define NT 4     // fixed rows per thread
#define NRED 32  // partial-reduce blocks (8 per batch)

// ---------------- scratch (no allocations allowed) ----------------
__device__ float g_pred_cp[B_*N_*CPD];
__device__ float g_gt_cp  [B_*N_*CPD];
__device__ float g_gt_c   [B_*N_*CPD];   // compacted succ gt rows (+pad)
__device__ int   g_cidx   [B_*N_];       // compact slot -> original index
__device__ int   g_nch    [B_];          // padded chunk count per batch
__device__ unsigned           g_best_u[B_*N_];  // pred->gt min (uint-ordered float)
__device__ unsigned long long g_k1[B_*N_];      // gt->pred packed (val,idx), normal
__device__ unsigned long long g_k2[B_*N_];      // gt->pred packed (val,idx), sym
__device__ float g_ew  [B_*N_];   // succ*(cos_d + cos_a + off)
__device__ float g_sbce[B_*N_];   // score bce per point
__device__ float g_part[NRED][5]; // per-block partials: s, ew, g2p, adds, bce

typedef unsigned long long ull;

__device__ __forceinline__ ull pack2(float lo, float hi) {
    ull r; asm("mov.b64 %0,{%1,%2};" : "=l"(r) : "f"(lo), "f"(hi)); return r;
}
__device__ __forceinline__ void unpack2(ull v, float& lo, float& hi) {
    asm("mov.b64 {%0,%1},%2;" : "=f"(lo), "=f"(hi) : "l"(v));
}
__device__ __forceinline__ ull fma2(ull a, ull b, ull c) {
    ull d; asm("fma.rn.f32x2 %0,%1,%2,%3;" : "=l"(d) : "l"(a), "l"(b), "l"(c)); return d;
}
__device__ __forceinline__ ull mul2(ull a, ull b) {
    ull d; asm("mul.rn.f32x2 %0,%1,%2;" : "=l"(d) : "l"(a), "l"(b)); return d;
}
__device__ __forceinline__ ull add2(ull a, ull b) {
    ull d; asm("add.rn.f32x2 %0,%1,%2;" : "=l"(d) : "l"(a), "l"(b)); return d;
}
__device__ __forceinline__ float softplusf(float x) {
    return fmaxf(x, 0.0f) + log1pf(expf(-fabsf(x)));
}
#define F_INF __int_as_float(0x7f800000)

// ---------------- kernel 1: build control points + elementwise + init ----------------
__global__ void prep_kernel(
    const float* __restrict__ gd, const float* __restrict__ ad,
    const float* __restrict__ goh, const float* __restrict__ pp,
    const float* __restrict__ bsh, const float* __restrict__ dl,
    const float* __restrict__ ol, const float* __restrict__ succ,
    const float* __restrict__ al, const float* __restrict__ bv,
    const float* __restrict__ bw, const float* __restrict__ cp)
{
    int i = blockIdx.x * blockDim.x + threadIdx.x;
    if (i >= B_ * N_) return;

    g_best_u[i] = 0x7f800000u;
    g_k1[i] = 0xFFFFFFFFFFFFFFFFull;
    g_k2[i] = 0xFFFFFFFFFFFFFFFFull;

    float bx = gd[i*3+0], by = gd[i*3+1], bz = gd[i*3+2];
    float ax = ad[i*3+0], ay = ad[i*3+1], az = ad[i*3+2];
    float px = pp[i*3+0], py = pp[i*3+1], pz = pp[i*3+2];

    int kp = 0; float xm = goh[i*NB_];
    #pragma unroll
    for (int k = 1; k < NB_; k++) { float v = goh[i*NB_+k]; if (v > xm) { xm = v; kp = k; } }
    float thp = bv[kp];

    int kg = 0; float ym = ol[i*NB_];
    #pragma unroll
    for (int k = 1; k < NB_; k++) { float v = ol[i*NB_+k]; if (v > ym) { ym = v; kg = k; } }
    float thg = bv[kg];

    float cx = ay*bz - az*by, cy = az*bx - ax*bz, cz = ax*by - ay*bx;
    float tx = px + 0.5f*thp*bx, ty = py + 0.5f*thp*by, tz = pz + 0.5f*thp*bz;
    {
        float row[16]; float nrm = 0.0f;
        #pragma unroll
        for (int p = 0; p < P_; p++) {
            float c0 = cp[p*3+0], c1 = cp[p*3+1], c2 = cp[p*3+2];
            float vx = bx*c0 + cx*c1 + ax*c2 + tx;
            float vy = by*c0 + cy*c1 + ay*c2 + ty;
            float vz = bz*c0 + cz*c1 + az*c2 + tz;
            row[p*3+0] = vx; row[p*3+1] = vy; row[p*3+2] = vz;
            nrm += vx*vx + vy*vy + vz*vz;
        }
        row[15] = nrm;
        float4* po = (float4*)(g_pred_cp + (size_t)i * CPD);
        #pragma unroll
        for (int q = 0; q < 4; q++) po[q] = make_float4(row[q*4], row[q*4+1], row[q*4+2], row[q*4+3]);
    }

    float gbx = dl[i*3+0], gby = dl[i*3+1], gbz = dl[i*3+2];
    float gax = al[i*3+0], gay = al[i*3+1], gaz = al[i*3+2];
    float gcx = gay*gbz - gaz*gby, gcy = gaz*gbx - gax*gbz, gcz = gax*gby - gay*gbx;
    float gtx = px + 0.5f*thg*gbx, gty = py + 0.5f*thg*gby, gtz = pz + 0.5f*thg*gbz;
    {
        float row[16]; float nrm = 0.0f;
        #pragma unroll
        for (int p = 0; p < P_; p++) {
            float c0 = cp[p*3+0], c1 = cp[p*3+1], c2 = cp[p*3+2];
            float vx = gbx*c0 + gcx*c1 + gax*c2 + gtx;
            float vy = gby*c0 + gcy*c1 + gay*c2 + gty;
            float vz = gbz*c0 + gcz*c1 + gaz*c2 + gtz;
            row[p*3+0] = vx; row[p*3+1] = vy; row[p*3+2] = vz;
            nrm += vx*vx + vy*vy + vz*vz;
        }
        row[15] = nrm;
        float4* go = (float4*)(g_gt_cp + (size_t)i * CPD);
        #pragma unroll
        for (int q = 0; q < 4; q++) go[q] = make_float4(row[q*4], row[q*4+1], row[q*4+2], row[q*4+3]);
    }

    float s = succ[i];
    float cos_d = 1.0f - (gbx*bx + gby*by + gbz*bz);
    float proj = bx*gax + by*gay + bz*gaz;
    float ox = gax - proj*bx, oy = gay - proj*by, oz = gaz - proj*bz;
    float on = sqrtf(ox*ox + oy*oy + oz*oz);
    float inv = 1.0f / fmaxf(on, 1e-12f);
    float cos_a = 1.0f - (ox*ax + oy*ay + oz*az) * inv;

    float off = 0.0f;
    #pragma unroll
    for (int k = 0; k < NB_; k++) {
        float x = goh[i*NB_+k], y = ol[i*NB_+k];
        off += bw[k] * (y * softplusf(-x) + (1.0f - y) * softplusf(x));
    }
    off *= (1.0f / NB_);

    g_ew[i] = s * (cos_d + cos_a + off);
    float h = bsh[i];
    g_sbce[i] = s * softplusf(-h) + (1.0f - s) * softplusf(h);
}

// ---------------- kernel 1b: compact succ gt rows (per-batch scan) ----------------
__global__ void compact_kernel(const float* __restrict__ succ)
{
    int b = blockIdx.x;
    int tid = threadIdx.x;                 // 1024 threads, 2 elems each
    int i0 = 2*tid, i1 = 2*tid + 1;
    int f0 = succ[(size_t)b*N_ + i0] > 0.5f;
    int f1 = succ[(size_t)b*N_ + i1] > 0.5f;
    int sum = f0 + f1;

    int lane = tid & 31, w = tid >> 5;
    int v = sum;
    #pragma unroll
    for (int o = 1; o < 32; o <<= 1) {
        int u = __shfl_up_sync(0xffffffffu, v, o);
        if (lane >= o) v += u;
    }
    __shared__ int wtot[32];
    if (lane == 31) wtot[w] = v;
    __syncthreads();
    if (w == 0) {
        int t = wtot[lane];
        #pragma unroll
        for (int o = 1; o < 32; o <<= 1) {
            int u = __shfl_up_sync(0xffffffffu, t, o);
            if (lane >= o) t += u;
        }
        wtot[lane] = t;
    }
    __syncthreads();
    int excl = v - sum + (w > 0 ? wtot[w-1] : 0);

    if (f0) {
        const float4* src = (const float4*)(g_gt_cp + ((size_t)b*N_ + i0) * CPD);
        float4* dst = (float4*)(g_gt_c + ((size_t)b*N_ + excl) * CPD);
        dst[0] = src[0]; dst[1] = src[1]; dst[2] = src[2]; dst[3] = src[3];
        g_cidx[(size_t)b*N_ + excl] = i0;
    }
    if (f1) {
        int p = excl + f0;
        const float4* src = (const float4*)(g_gt_cp + ((size_t)b*N_ + i1) * CPD);
        float4* dst = (float4*)(g_gt_c + ((size_t)b*N_ + p) * CPD);
        dst[0] = src[0]; dst[1] = src[1]; dst[2] = src[2]; dst[3] = src[3];
        g_cidx[(size_t)b*N_ + p] = i1;
    }

    int cnt = wtot[31];
    int pad = (cnt + CH - 1) / CH * CH;
    for (int p = cnt + tid; p < pad; p += 1024) {
        float4* d = (float4*)(g_gt_c + ((size_t)b*N_ + p) * CPD);
        d[0] = make_float4(0,0,0,0);
        d[1] = make_float4(0,0,0,0);
        d[2] = make_float4(0,0,0,0);
        d[3] = make_float4(0,0,0,F_INF);
        g_cidx[(size_t)b*N_ + p] = 0;
    }
    if (tid == 0) g_nch[b] = pad / CH;
}

// ---------------- kernel 2: pairwise, both directions, balanced splits ----------------
// grid (16, B_, 6):
//   z in {0,1}: dir A, stream-half z.   fixed = all 2048 pred rows (16 x-blocks),
//               streamed = compacted gt chunks c = z, z+2, ... -> masked min.
//   z in {2..5}: dir B, stream-quarter z-2. fixed = compacted gt rows
//               (x-blocks with row0 < padcnt), streamed = pred chunks -> argmin keys.
__global__ __launch_bounds__(256, 2) void pair_kernel(const float* __restrict__ bsp)
{
    __shared__ float4 sg[CH*5];            // stride-5 padding: conflict-free
    int b    = blockIdx.y;
    int z    = blockIdx.z;
    int tid  = threadIdx.x;
    int ns   = tid >> 3;
    int ml   = tid & 7;

    if (z < 2) {
        // ---------------- direction A ----------------
        int half = z;
        ull FP[NT][7];
        float f14[NT], fn[NT], fD0[NT], fD1[NT], fD2[NT];
        int nrow[NT];
        #pragma unroll
        for (int r = 0; r < NT; r++) {
            int n = blockIdx.x * (32*NT) + r*32 + ns;
            nrow[r] = n;
            const float4* row = (const float4*)(g_pred_cp + ((size_t)b*N_ + n) * CPD);
            float4 a0 = row[0], a1 = row[1], a2 = row[2], a3 = row[3];
            FP[r][0] = pack2(a0.x, a0.y); FP[r][1] = pack2(a0.z, a0.w);
            FP[r][2] = pack2(a1.x, a1.y); FP[r][3] = pack2(a1.z, a1.w);
            FP[r][4] = pack2(a2.x, a2.y); FP[r][5] = pack2(a2.z, a2.w);
            FP[r][6] = pack2(a3.x, a3.y);
            f14[r] = a3.z; fn[r] = a3.w;
            fD0[r] = a1.z - a2.y; fD1[r] = a1.w - a2.z; fD2[r] = a2.x - a2.w;
        }
        float minv[NT];
        #pragma unroll
        for (int r = 0; r < NT; r++) minv[r] = F_INF;

        int nch = g_nch[b];
        for (int c = half; c < nch; c += 2) {
            int mc = c * CH;
            __syncthreads();
            const float4* src = (const float4*)(g_gt_c + ((size_t)b*N_ + mc) * CPD);
            #pragma unroll
            for (int j = tid; j < CH*4; j += 256) sg[(j >> 2) * 5 + (j & 3)] = src[j];
            __syncthreads();

            #pragma unroll 2
            for (int j = 0; j < CH/8; j++) {
                int m = ml + j*8;
                const float4* sp = &sg[m*5];
                float4 s0 = sp[0], s1 = sp[1], s2 = sp[2], s3 = sp[3];
                ull S0 = pack2(s0.x, s0.y), S1 = pack2(s0.z, s0.w);
                ull S2 = pack2(s1.x, s1.y), S3 = pack2(s1.z, s1.w);
                ull S4 = pack2(s2.x, s2.y), S5 = pack2(s2.z, s2.w);
                ull S6 = pack2(s3.x, s3.y);
                float s14 = s3.z, sn = s3.w;
                float D0 = s1.z - s2.y, D1 = s1.w - s2.z, D2 = s2.x - s2.w;

                #pragma unroll
                for (int r = 0; r < NT; r++) {
                    ull a = mul2(FP[r][0], S0);
                    ull cc = mul2(FP[r][1], S1);
                    a = fma2(FP[r][2], S2, a);
                    cc = fma2(FP[r][3], S3, cc);
                    a = fma2(FP[r][4], S4, a);
                    cc = fma2(FP[r][5], S5, cc);
                    a = fma2(FP[r][6], S6, a);
                    a = add2(a, cc);
                    float lo, hi; unpack2(a, lo, hi);
                    float dot = fmaf(f14[r], s14, lo + hi);
                    float d1 = fmaf(-2.0f, dot, fn[r] + sn);
                    float corr = fD0[r] * D0;
                    corr = fmaf(fD1[r], D1, corr);
                    corr = fmaf(fD2[r], D2, corr);
                    float d2 = fmaf(2.0f, corr, d1);
                    float dm = fminf(fmaxf(d1, 0.0f), fmaxf(d2, 0.0f));
                    minv[r] = fminf(minv[r], dm);
                }
            }
        }
        #pragma unroll
        for (int r = 0; r < NT; r++) {
            float v = minv[r];
            v = fminf(v, __shfl_down_sync(0xffffffffu, v, 4));
            v = fminf(v, __shfl_down_sync(0xffffffffu, v, 2));
            v = fminf(v, __shfl_down_sync(0xffffffffu, v, 1));
            if (ml == 0)
                atomicMin(&g_best_u[(size_t)b*N_ + nrow[r]], __float_as_uint(v));
        }
    } else {
        // ---------------- direction B ----------------
        int quart = z - 2;
        int padcnt = g_nch[b] * CH;
        int row0 = blockIdx.x * (32*NT);
        if (row0 >= padcnt) return;

        ull FP[NT][7];
        float f14[NT], fn[NT], fD0[NT], fD1[NT], fD2[NT];
        int orig[NT];
        #pragma unroll
        for (int r = 0; r < NT; r++) {
            int n = row0 + r*32 + ns;
            orig[r] = g_cidx[(size_t)b*N_ + n];
            const float4* row = (const float4*)(g_gt_c + ((size_t)b*N_ + n) * CPD);
            float4 a0 = row[0], a1 = row[1], a2 = row[2], a3 = row[3];
            FP[r][0] = pack2(a0.x, a0.y); FP[r][1] = pack2(a0.z, a0.w);
            FP[r][2] = pack2(a1.x, a1.y); FP[r][3] = pack2(a1.z, a1.w);
            FP[r][4] = pack2(a2.x, a2.y); FP[r][5] = pack2(a2.z, a2.w);
            FP[r][6] = pack2(a3.x, a3.y);
            f14[r] = a3.z; fn[r] = a3.w;
            fD0[r] = a1.z - a2.y; fD1[r] = a1.w - a2.z; fD2[r] = a2.x - a2.w;
        }
        ull b1[NT], b2[NT];
        #pragma unroll
        for (int r = 0; r < NT; r++) { b1[r] = ~0ull; b2[r] = ~0ull; }

        for (int c = quart; c < N_/CH; c += 4) {
            int mc = c * CH;
            __syncthreads();
            const float4* src = (const float4*)(g_pred_cp + ((size_t)b*N_ + mc) * CPD);
            #pragma unroll
            for (int j = tid; j < CH*4; j += 256) sg[(j >> 2) * 5 + (j & 3)] = src[j];
            __syncthreads();

            #pragma unroll 2
            for (int j = 0; j < CH/8; j++) {
                int m = ml + j*8;
                const float4* sp = &sg[m*5];
                float4 s0 = sp[0], s1 = sp[1], s2 = sp[2], s3 = sp[3];
                ull S0 = pack2(s0.x, s0.y), S1 = pack2(s0.z, s0.w);
                ull S2 = pack2(s1.x, s1.y), S3 = pack2(s1.z, s1.w);
                ull S4 = pack2(s2.x, s2.y), S5 = pack2(s2.z, s2.w);
                ull S6 = pack2(s3.x, s3.y);
                float s14 = s3.z, sn = s3.w;
                float D0 = s1.z - s2.y, D1 = s1.w - s2.z, D2 = s2.x - s2.w;
                unsigned idx = (unsigned)(mc + m);

                #pragma unroll
                for (int r = 0; r < NT; r++) {
                    ull a = mul2(FP[r][0], S0);
                    ull cc = mul2(FP[r][1], S1);
                    a = fma2(FP[r][2], S2, a);
                    cc = fma2(FP[r][3], S3, cc);
                    a = fma2(FP[r][4], S4, a);
                    cc = fma2(FP[r][5], S5, cc);
                    a = fma2(FP[r][6], S6, a);
                    a = add2(a, cc);
                    float lo, hi; unpack2(a, lo, hi);
                    float dot = fmaf(f14[r], s14, lo + hi);
                    float d1 = fmaf(-2.0f, dot, fn[r] + sn);
                    float corr = fD0[r] * D0;
                    corr = fmaf(fD1[r], D1, corr);
                    corr = fmaf(fD2[r], D2, corr);
                    float d2 = fmaf(2.0f, corr, d1);
                    d1 = fmaxf(d1, 0.0f);
                    d2 = fmaxf(d2, 0.0f);
                    ull k1 = ((ull)__float_as_uint(d1) << 32) | idx;
                    ull k2 = ((ull)__float_as_uint(d2) << 32) | idx;
                    if (k1 < b1[r]) b1[r] = k1;
                    if (k2 < b2[r]) b2[r] = k2;
                }
            }
        }
        #pragma unroll
        for (int r = 0; r < NT; r++) {
            ull v1 = b1[r], v2 = b2[r], o;
            o = __shfl_down_sync(0xffffffffu, v1, 4); if (o < v1) v1 = o;
            o = __shfl_down_sync(0xffffffffu, v1, 2); if (o < v1) v1 = o;
            o = __shfl_down_sync(0xffffffffu, v1, 1); if (o < v1) v1 = o;
            o = __shfl_down_sync(0xffffffffu, v2, 4); if (o < v2) v2 = o;
            o = __shfl_down_sync(0xffffffffu, v2, 2); if (o < v2) v2 = o;
            o = __shfl_down_sync(0xffffffffu, v2, 1); if (o < v2) v2 = o;
            if (ml == 0) {
                atomicMin(&g_k1[(size_t)b*N_ + orig[r]], v1);
                atomicMin(&g_k2[(size_t)b*N_ + orig[r]], v2);
            }
        }
    }
}

// ---------------- kernel 3a: partial reduce (32 blocks x 256, 1 elem/thread) ----------------
__global__ void reduce1_kernel(const float* __restrict__ succ,
                               const float* __restrict__ bsp)
{
    int i = blockIdx.x * 256 + threadIdx.x;   // block -> contiguous 256, same batch
    int b = i >> 11;
    float sv = succ[i];
    float ev = g_ew[i];

    float gv = 0.0f;
    if (sv > 0.5f) {
        ull k1 = g_k1[i], k2 = g_k2[i];
        float m1 = __uint_as_float((unsigned)(k1 >> 32));
        float m2 = __uint_as_float((unsigned)(k2 >> 32));
        int i1 = (int)(k1 & 0xFFFFFFFFu);
        int i2 = (int)(k2 & 0xFFFFFFFFu);
        int idx = (m2 < m1) ? i2 : i1;
        gv = sv * bsp[(size_t)b*N_ + idx] * fminf(m1, m2);
    }

    unsigned bu = g_best_u[i];
    float ma = (bu == 0x7f800000u) ? 0.0f : sqrtf(__uint_as_float(bu));
    float av = bsp[i] * ma;
    float cv = g_sbce[i];

    #define WR(v) { v += __shfl_xor_sync(0xffffffffu, v, 16); \
                    v += __shfl_xor_sync(0xffffffffu, v, 8);  \
                    v += __shfl_xor_sync(0xffffffffu, v, 4);  \
                    v += __shfl_xor_sync(0xffffffffu, v, 2);  \
                    v += __shfl_xor_sync(0xffffffffu, v, 1); }
    WR(sv) WR(ev) WR(gv) WR(av) WR(cv)
    #undef WR

    __shared__ float red[8][5];
    int w = threadIdx.x >> 5, l = threadIdx.x & 31;
    if (l == 0) { red[w][0]=sv; red[w][1]=ev; red[w][2]=gv; red[w][3]=av; red[w][4]=cv; }
    __syncthreads();
    if (threadIdx.x < 5) {
        int k = threadIdx.x;
        float a = 0.f;
        #pragma unroll
        for (int w2 = 0; w2 < 8; w2++) a += red[w2][k];
        g_part[blockIdx.x][k] = a;
    }
}

// ---------------- kernel 3b: combine (1 warp; 8 blocks per batch) ----------------
__global__ void reduce2_kernel(float* __restrict__ out)
{
    int t = threadIdx.x;  // 32 threads, each carries one partial row
    float s = g_part[t][0], e = g_part[t][1], g = g_part[t][2];
    float ad = g_part[t][3], bc = g_part[t][4];

    // per-batch sums: groups of 8 consecutive lanes
    s += __shfl_xor_sync(0xffffffffu, s, 1); s += __shfl_xor_sync(0xffffffffu, s, 2); s += __shfl_xor_sync(0xffffffffu, s, 4);
    e += __shfl_xor_sync(0xffffffffu, e, 1); e += __shfl_xor_sync(0xffffffffu, e, 2); e += __shfl_xor_sync(0xffffffffu, e, 4);
    g += __shfl_xor_sync(0xffffffffu, g, 1); g += __shfl_xor_sync(0xffffffffu, g, 2); g += __shfl_xor_sync(0xffffffffu, g, 4);
    // global sums
    ad += __shfl_xor_sync(0xffffffffu, ad, 1); ad += __shfl_xor_sync(0xffffffffu, ad, 2);
    ad += __shfl_xor_sync(0xffffffffu, ad, 4); ad += __shfl_xor_sync(0xffffffffu, ad, 8);
    ad += __shfl_xor_sync(0xffffffffu, ad, 16);
    bc += __shfl_xor_sync(0xffffffffu, bc, 1); bc += __shfl_xor_sync(0xffffffffu, bc, 2);
    bc += __shfl_xor_sync(0xffffffffu, bc, 4); bc += __shfl_xor_sync(0xffffffffu, bc, 8);
    bc += __shfl_xor_sync(0xffffffffu, bc, 16);

    float S0 = __shfl_sync(0xffffffffu, s, 0),  E0 = __shfl_sync(0xffffffffu, e, 0),  G0 = __shfl_sync(0xffffffffu, g, 0);
    float S1 = __shfl_sync(0xffffffffu, s, 8),  E1 = __shfl_sync(0xffffffffu, e, 8),  G1 = __shfl_sync(0xffffffffu, g, 8);
    float S2 = __shfl_sync(0xffffffffu, s, 16), E2 = __shfl_sync(0xffffffffu, e, 16), G2 = __shfl_sync(0xffffffffu, g, 16);
    float S3 = __shfl_sync(0xffffffffu, s, 24), E3 = __shfl_sync(0xffffffffu, e, 24), G3 = __shfl_sync(0xffffffffu, g, 24);

    if (t == 0) {
        float tot = (E0 + G0) / fmaxf(S0, 1.0f)
                  + (E1 + G1) / fmaxf(S1, 1.0f)
                  + (E2 + G2) / fmaxf(S2, 1.0f)
                  + (E3 + G3) / fmaxf(S3, 1.0f);
        tot *= (1.0f / B_);
        tot += 10.0f * ad * (1.0f / (B_ * N_));
        tot += bc * (1.0f / (B_ * N_));
        out[0] = tot;
    }
}

// ---------------- launch ----------------
extern "C" void kernel_launch(void* const* d_in, const int* in_sizes, int n_in,
                              void* d_out, int out_size)
{
    const float* gd   = (const float*)d_in[0];
    const float* ad   = (const float*)d_in[1];
    const float* goh  = (const float*)d_in[2];
    const float* pp   = (const float*)d_in[3];
    const float* bsp  = (const float*)d_in[4];
    const float* bsh  = (const float*)d_in[5];
    const float* dl   = (const float*)d_in[6];
    const float* ol   = (const float*)d_in[7];
    const float* succ = (const float*)d_in[8];
    const float* al   = (const float*)d_in[9];
    const float* bv   = (const float*)d_in[10];
    const float* bw   = (const float*)d_in[11];
    const float* cp   = (const float*)d_in[12];
    float* out = (float*)d_out;

    prep_kernel<<<(B_*N_ + 63) / 64, 64>>>(gd, ad, goh, pp, bsh, dl, ol, succ, al, bv, bw, cp);
    compact_kernel<<<B_, 1024>>>(succ);
    dim3 grid2(N_ / (32*NT), B_, 6);
    pair_kernel<<<grid2, 256>>>(bsp);
    reduce1_kernel<<<NRED, 256>>>(succ, bsp);
    reduce2_kernel<<<1, 32>>>(out);
}